// round 1
// baseline (speedup 1.0000x reference)
#include <cuda_runtime.h>
#include <math.h>

// Problem dims (fixed)
#define L_    2048
#define B_    2
#define D_    1024
#define H_    16
#define HD_   64
#define DFF_  4096
#define MTOK  4096   // L*B tokens

// ---------------------------------------------------------------------------
// Scratch (static device globals; allocation inside kernel_launch is banned)
// ---------------------------------------------------------------------------
__device__ float g_h [(size_t)MTOK * D_];    // LN output (reused for LN1 and LN2)
__device__ float g_q [(size_t)B_ * H_ * L_ * HD_];
__device__ float g_at[(size_t)MTOK * D_];    // attention output, token-major
__device__ float g_x1[(size_t)MTOK * D_];    // x + attn (residual 1)
__device__ float g_m [(size_t)MTOK * DFF_];  // gelu(fc) activations

// ---------------------------------------------------------------------------
// LayerNorm: one block per token row (1024 elems), 256 threads * float4
// ---------------------------------------------------------------------------
__global__ __launch_bounds__(256)
void ln_k(const float* __restrict__ x, const float* __restrict__ g,
          const float* __restrict__ b, float* __restrict__ out)
{
    const int row = blockIdx.x;
    const int tid = threadIdx.x;
    const float4 v = *(const float4*)(x + (size_t)row * D_ + tid * 4);

    float s = v.x + v.y + v.z + v.w;
    float q = v.x * v.x + v.y * v.y + v.z * v.z + v.w * v.w;
    #pragma unroll
    for (int o = 16; o > 0; o >>= 1) {
        s += __shfl_down_sync(0xffffffffu, s, o);
        q += __shfl_down_sync(0xffffffffu, q, o);
    }
    __shared__ float ss[8], sq[8];
    const int w = tid >> 5, ln = tid & 31;
    if (ln == 0) { ss[w] = s; sq[w] = q; }
    __syncthreads();
    float S = 0.f, Q = 0.f;
    #pragma unroll
    for (int i = 0; i < 8; i++) { S += ss[i]; Q += sq[i]; }

    const float mu  = S * (1.f / D_);
    const float var = Q * (1.f / D_) - mu * mu;
    const float rs  = rsqrtf(var + 1e-5f);

    const float4 gv = *(const float4*)(g + tid * 4);
    const float4 bv = *(const float4*)(b + tid * 4);
    float4 o;
    o.x = (v.x - mu) * rs * gv.x + bv.x;
    o.y = (v.y - mu) * rs * gv.y + bv.y;
    o.z = (v.z - mu) * rs * gv.z + bv.z;
    o.w = (v.w - mu) * rs * gv.w + bv.w;
    *(float4*)(out + (size_t)row * D_ + tid * 4) = o;
}

// ---------------------------------------------------------------------------
// Tiled SGEMM: C[M,N] = A[M,K] @ B[K,N] + bias, with fused epilogues.
//   EPI 0: scatter QKV -> q scratch / k,v (present region of d_out)
//   EPI 1: C = acc + bias + resid   (proj + residual, out + residual)
//   EPI 2: C = gelu(acc + bias)     (fc)
// BM=BN=128, BK=8, TM=TN=8, 256 threads. All dims divide evenly -> no guards.
// ---------------------------------------------------------------------------
template <int EPI>
__global__ __launch_bounds__(256)
void sgemm_k(const float* __restrict__ A, const float* __restrict__ Bm,
             const float* __restrict__ bias, const float* __restrict__ resid,
             float* __restrict__ C, int M, int N, int K,
             float* __restrict__ e0, float* __restrict__ e1, float* __restrict__ e2)
{
    constexpr int BM = 128, BN = 128, BK = 8, TM = 8, TN = 8;
    __shared__ float As[BK][BM];
    __shared__ float Bs[BK][BN];

    const int cRow = blockIdx.y, cCol = blockIdx.x;
    const int tid  = threadIdx.x;
    const int tCol = tid & 15;        // 0..15  -> TN*16 = 128 cols
    const int tRow = tid >> 4;        // 0..15  -> TM*16 = 128 rows
    const int aRow = tid >> 1;        // 0..127
    const int aCol = (tid & 1) * 4;   // 0 or 4
    const int bRow = tid >> 5;        // 0..7
    const int bCol = (tid & 31) * 4;  // 0..124

    const float* Ap = A  + (size_t)cRow * BM * K;
    const float* Bp = Bm + cCol * BN;

    float acc[TM][TN];
    #pragma unroll
    for (int i = 0; i < TM; i++)
        #pragma unroll
        for (int j = 0; j < TN; j++) acc[i][j] = 0.f;

    for (int k0 = 0; k0 < K; k0 += BK) {
        const float4 a4 = *(const float4*)(Ap + (size_t)aRow * K + k0 + aCol);
        As[aCol + 0][aRow] = a4.x;
        As[aCol + 1][aRow] = a4.y;
        As[aCol + 2][aRow] = a4.z;
        As[aCol + 3][aRow] = a4.w;
        *(float4*)&Bs[bRow][bCol] =
            *(const float4*)(Bp + (size_t)(k0 + bRow) * N + bCol);
        __syncthreads();

        #pragma unroll
        for (int kk = 0; kk < BK; kk++) {
            float regM[TM], regN[TN];
            *(float4*)&regM[0] = *(const float4*)&As[kk][tRow * TM];
            *(float4*)&regM[4] = *(const float4*)&As[kk][tRow * TM + 4];
            *(float4*)&regN[0] = *(const float4*)&Bs[kk][tCol * TN];
            *(float4*)&regN[4] = *(const float4*)&Bs[kk][tCol * TN + 4];
            #pragma unroll
            for (int i = 0; i < TM; i++)
                #pragma unroll
                for (int j = 0; j < TN; j++)
                    acc[i][j] += regM[i] * regN[j];
        }
        __syncthreads();
    }

    #pragma unroll
    for (int i = 0; i < TM; i++) {
        const int m = cRow * BM + tRow * TM + i;
        #pragma unroll
        for (int j = 0; j < TN; j++) {
            const int n = cCol * BN + tCol * TN + j;
            float v = acc[i][j] + bias[n];
            if (EPI == 0) {
                // n in [0,3D): part selects q/k/v; scatter to [B,H,L,HD]
                const int part = n >> 10;
                const int d  = n & 1023;
                const int hh = d >> 6;
                const int hd = d & 63;
                const int l  = m >> 1;      // token row m = l*B + b, B = 2
                const int bb = m & 1;
                const size_t idx =
                    (((size_t)(bb * H_ + hh) * L_) + l) * HD_ + hd;
                if      (part == 0) e0[idx] = v;
                else if (part == 1) e1[idx] = v;
                else                e2[idx] = v;
            } else if (EPI == 1) {
                const size_t idx = (size_t)m * N + n;
                C[idx] = v + resid[idx];
            } else { // EPI == 2: tanh-approx GELU (JAX default approximate=True)
                const float t = tanhf(0.7978845608028654f *
                                      (v + 0.044715f * v * v * v));
                C[(size_t)m * N + n] = 0.5f * v * (1.f + t);
            }
        }
    }
}

// ---------------------------------------------------------------------------
// Flash attention (fp32). One thread owns one q row (HD=64 in registers).
// KV tiles of 16 rows staged in smem; online softmax (running max/sum).
// grid = (L/128, B*H), block = 128.
// ---------------------------------------------------------------------------
#define KT 16

__global__ __launch_bounds__(128)
void attn_k(const float* __restrict__ q, const float* __restrict__ k,
            const float* __restrict__ v, float* __restrict__ out)
{
    const int bh   = blockIdx.y;          // b*H + h
    const int b    = bh >> 4;
    const int h    = bh & 15;
    const int qrow = blockIdx.x * 128 + threadIdx.x;

    __shared__ float Ks[KT][HD_];
    __shared__ float Vs[KT][HD_];

    float qr[HD_];
    {
        const float* qp = q + ((size_t)bh * L_ + qrow) * HD_;
        #pragma unroll
        for (int d = 0; d < HD_; d += 4) {
            const float4 t = *(const float4*)(qp + d);
            qr[d + 0] = t.x * 0.125f;     // 1/sqrt(64) folded into q
            qr[d + 1] = t.y * 0.125f;
            qr[d + 2] = t.z * 0.125f;
            qr[d + 3] = t.w * 0.125f;
        }
    }

    float o[HD_];
    #pragma unroll
    for (int d = 0; d < HD_; d++) o[d] = 0.f;
    float mrun = -1e30f, lsum = 0.f;

    const float* kbase = k + (size_t)bh * L_ * HD_;
    const float* vbase = v + (size_t)bh * L_ * HD_;

    for (int t0 = 0; t0 < L_; t0 += KT) {
        // cooperative load: KT*64 = 1024 floats = 256 float4 per matrix
        {
            const int fi = (int)threadIdx.x;          // 128 threads, 2 float4 each
            #pragma unroll
            for (int i = 0; i < 2; i++) {
                const int idx = i * 128 + fi;          // float4 index
                const int r = idx >> 4, c = (idx & 15) * 4;
                *(float4*)&Ks[r][c] = *(const float4*)(kbase + (size_t)t0 * HD_ + idx * 4);
                *(float4*)&Vs[r][c] = *(const float4*)(vbase + (size_t)t0 * HD_ + idx * 4);
            }
        }
        __syncthreads();

        float s[KT];
        float tmax = mrun;
        #pragma unroll
        for (int j = 0; j < KT; j++) {
            float a0 = 0.f, a1 = 0.f, a2 = 0.f, a3 = 0.f;
            #pragma unroll
            for (int d = 0; d < HD_; d += 4) {
                const float4 kv = *(const float4*)&Ks[j][d];
                a0 += qr[d + 0] * kv.x;
                a1 += qr[d + 1] * kv.y;
                a2 += qr[d + 2] * kv.z;
                a3 += qr[d + 3] * kv.w;
            }
            const float sj = (a0 + a1) + (a2 + a3);
            s[j] = sj;
            tmax = fmaxf(tmax, sj);
        }

        const float corr = __expf(mrun - tmax);
        lsum *= corr;
        #pragma unroll
        for (int d = 0; d < HD_; d++) o[d] *= corr;

        #pragma unroll
        for (int j = 0; j < KT; j++) {
            const float p = __expf(s[j] - tmax);
            lsum += p;
            #pragma unroll
            for (int d = 0; d < HD_; d += 4) {
                const float4 vv = *(const float4*)&Vs[j][d];
                o[d + 0] += p * vv.x;
                o[d + 1] += p * vv.y;
                o[d + 2] += p * vv.z;
                o[d + 3] += p * vv.w;
            }
        }
        mrun = tmax;
        __syncthreads();
    }

    const float inv = 1.f / lsum;
    // token-major output: row = qrow*B + b, col = h*64 + d
    float* op = out + ((size_t)qrow * B_ + b) * D_ + h * HD_;
    #pragma unroll
    for (int d = 0; d < HD_; d += 4) {
        float4 t;
        t.x = o[d + 0] * inv;
        t.y = o[d + 1] * inv;
        t.z = o[d + 2] * inv;
        t.w = o[d + 3] * inv;
        *(float4*)(op + d) = t;
    }
}

// ---------------------------------------------------------------------------
// Launch
// ---------------------------------------------------------------------------
extern "C" void kernel_launch(void* const* d_in, const int* in_sizes, int n_in,
                              void* d_out, int out_size)
{
    const float* x      = (const float*)d_in[0];
    const float* ln1_g  = (const float*)d_in[1];
    const float* ln1_b  = (const float*)d_in[2];
    const float* w_attn = (const float*)d_in[3];
    const float* b_attn = (const float*)d_in[4];
    const float* w_proj = (const float*)d_in[5];
    const float* b_proj = (const float*)d_in[6];
    const float* ln2_g  = (const float*)d_in[7];
    const float* ln2_b  = (const float*)d_in[8];
    const float* w_fc   = (const float*)d_in[9];
    const float* b_fc   = (const float*)d_in[10];
    const float* w_out  = (const float*)d_in[11];
    const float* b_out  = (const float*)d_in[12];

    float* out  = (float*)d_out;
    float* kout = out  + (size_t)L_ * B_ * D_;                 // present[0]
    float* vout = kout + (size_t)B_ * H_ * L_ * HD_;           // present[1]

    float *hptr, *qptr, *atptr, *x1ptr, *mptr;
    cudaGetSymbolAddress((void**)&hptr,  g_h);
    cudaGetSymbolAddress((void**)&qptr,  g_q);
    cudaGetSymbolAddress((void**)&atptr, g_at);
    cudaGetSymbolAddress((void**)&x1ptr, g_x1);
    cudaGetSymbolAddress((void**)&mptr,  g_m);

    // 1) LN1
    ln_k<<<MTOK, 256>>>(x, ln1_g, ln1_b, hptr);

    // 2) QKV GEMM [4096,1024]@[1024,3072]; scatter q->scratch, k/v->present
    sgemm_k<0><<<dim3(3 * D_ / 128, MTOK / 128), 256>>>(
        hptr, w_attn, b_attn, nullptr, nullptr, MTOK, 3 * D_, D_,
        qptr, kout, vout);

    // 3) attention -> token-major a
    attn_k<<<dim3(L_ / 128, B_ * H_), 128>>>(qptr, kout, vout, atptr);

    // 4) proj + residual -> x1
    sgemm_k<1><<<dim3(D_ / 128, MTOK / 128), 256>>>(
        atptr, w_proj, b_proj, x, x1ptr, MTOK, D_, D_,
        nullptr, nullptr, nullptr);

    // 5) LN2
    ln_k<<<MTOK, 256>>>(x1ptr, ln2_g, ln2_b, hptr);

    // 6) FC + GELU
    sgemm_k<2><<<dim3(DFF_ / 128, MTOK / 128), 256>>>(
        hptr, w_fc, b_fc, nullptr, mptr, MTOK, DFF_, D_,
        nullptr, nullptr, nullptr);

    // 7) out proj + residual -> final x
    sgemm_k<1><<<dim3(D_ / 128, MTOK / 128), 256>>>(
        mptr, w_out, b_out, x1ptr, out, MTOK, D_, DFF_,
        nullptr, nullptr, nullptr);
}

// round 3
// speedup vs baseline: 1.7197x; 1.7197x over previous
#include <cuda_runtime.h>
#include <math.h>
#include <stdint.h>

// Problem dims (fixed)
#define L_    2048
#define B_    2
#define D_    1024
#define H_    16
#define HD_   64
#define DFF_  4096
#define MTOK  4096   // L*B tokens

// ---------------------------------------------------------------------------
// Scratch (static device globals; allocation inside kernel_launch is banned)
// ---------------------------------------------------------------------------
__device__ float g_h [(size_t)MTOK * D_];    // LN output (reused for LN1 and LN2)
__device__ float g_q [(size_t)B_ * H_ * L_ * HD_];
__device__ float g_at[(size_t)MTOK * D_];    // attention output, token-major
__device__ float g_x1[(size_t)MTOK * D_];    // x + attn (residual 1)
__device__ float g_m [(size_t)MTOK * DFF_];  // gelu(fc) activations

// ---------------------------------------------------------------------------
// tf32 helpers (baseline PTX only — no tcgen05 on this build: PTX target is
// compute_103 without the 'a' suffix, so arch-accelerated features are out)
// ---------------------------------------------------------------------------
__device__ __forceinline__ uint32_t tf32r(float f) {
    uint32_t r;
    asm("cvt.rna.tf32.f32 %0, %1;" : "=r"(r) : "f"(f));
    return r;
}
__device__ __forceinline__ uint4 tf32x4(float4 v) {
    return make_uint4(tf32r(v.x), tf32r(v.y), tf32r(v.z), tf32r(v.w));
}

#define MMA_TF32(d, a, b)                                                   \
    asm volatile(                                                           \
        "mma.sync.aligned.m16n8k8.row.col.f32.tf32.tf32.f32 "               \
        "{%0,%1,%2,%3}, {%4,%5,%6,%7}, {%8,%9}, {%0,%1,%2,%3};"             \
        : "+f"((d)[0]), "+f"((d)[1]), "+f"((d)[2]), "+f"((d)[3])            \
        : "r"((a)[0]), "r"((a)[1]), "r"((a)[2]), "r"((a)[3]),               \
          "r"((b)[0]), "r"((b)[1]))

// ---------------------------------------------------------------------------
// LayerNorm: one block per token row (1024 elems), 256 threads * float4
// ---------------------------------------------------------------------------
__global__ __launch_bounds__(256)
void ln_k(const float* __restrict__ x, const float* __restrict__ g,
          const float* __restrict__ b, float* __restrict__ out)
{
    const int row = blockIdx.x;
    const int tid = threadIdx.x;
    const float4 v = *(const float4*)(x + (size_t)row * D_ + tid * 4);

    float s = v.x + v.y + v.z + v.w;
    float q = v.x * v.x + v.y * v.y + v.z * v.z + v.w * v.w;
    #pragma unroll
    for (int o = 16; o > 0; o >>= 1) {
        s += __shfl_down_sync(0xffffffffu, s, o);
        q += __shfl_down_sync(0xffffffffu, q, o);
    }
    __shared__ float ss[8], sq[8];
    const int w = tid >> 5, ln = tid & 31;
    if (ln == 0) { ss[w] = s; sq[w] = q; }
    __syncthreads();
    float S = 0.f, Q = 0.f;
    #pragma unroll
    for (int i = 0; i < 8; i++) { S += ss[i]; Q += sq[i]; }

    const float mu  = S * (1.f / D_);
    const float var = Q * (1.f / D_) - mu * mu;
    const float rs  = rsqrtf(var + 1e-5f);

    const float4 gv = *(const float4*)(g + tid * 4);
    const float4 bv = *(const float4*)(b + tid * 4);
    float4 o;
    o.x = (v.x - mu) * rs * gv.x + bv.x;
    o.y = (v.y - mu) * rs * gv.y + bv.y;
    o.z = (v.z - mu) * rs * gv.z + bv.z;
    o.w = (v.w - mu) * rs * gv.w + bv.w;
    *(float4*)(out + (size_t)row * D_ + tid * 4) = o;
}

// ---------------------------------------------------------------------------
// Epilogue helper: consume one float2 at (m, n), n even.
//   EPI 0: scatter QKV -> q scratch / k,v (present region of d_out)
//   EPI 1: C = acc + bias + resid
//   EPI 2: C = gelu(acc + bias)
// ---------------------------------------------------------------------------
template <int EPI>
__device__ __forceinline__ void epi_store(
    int m, int n, float2 v, int N,
    const float* __restrict__ bias, const float* __restrict__ resid,
    float* __restrict__ C,
    float* __restrict__ e0, float* __restrict__ e1, float* __restrict__ e2)
{
    const float2 bv = *(const float2*)(bias + n);
    v.x += bv.x;
    v.y += bv.y;
    if (EPI == 0) {
        const int part = n >> 10;
        const int d    = n & 1023;
        const int hh   = d >> 6;
        const int hd   = d & 63;
        const int l    = m >> 1;     // token m = l*B + b, B=2
        const int bb   = m & 1;
        const size_t idx = (((size_t)(bb * H_ + hh) * L_) + l) * HD_ + hd;
        float* dst = (part == 0) ? e0 : (part == 1) ? e1 : e2;
        *(float2*)(dst + idx) = v;
    } else if (EPI == 1) {
        const size_t idx = (size_t)m * N + n;
        const float2 rv = *(const float2*)(resid + idx);
        v.x += rv.x;
        v.y += rv.y;
        *(float2*)(C + idx) = v;
    } else {
        float2 o;
        const float t0 = tanhf(0.7978845608028654f *
                               (v.x + 0.044715f * v.x * v.x * v.x));
        o.x = 0.5f * v.x * (1.f + t0);
        const float t1 = tanhf(0.7978845608028654f *
                               (v.y + 0.044715f * v.y * v.y * v.y));
        o.y = 0.5f * v.y * (1.f + t1);
        *(float2*)(C + (size_t)m * N + n) = o;
    }
}

// ---------------------------------------------------------------------------
// tf32 mma.sync GEMM: C[M,N] = A[M,K] @ B[K,N] (+bias, fused epilogue).
// CTA 128x128, BK=16, 256 threads (8 warps, 4x2 grid, warp tile 32x64).
// Smem padded conflict-free; global loads software-pipelined via registers.
// ---------------------------------------------------------------------------
template <int EPI>
__global__ __launch_bounds__(256, 2)
void mgemm_k(const float* __restrict__ A, const float* __restrict__ Bm,
             const float* __restrict__ bias, const float* __restrict__ resid,
             float* __restrict__ C, int M, int N, int K,
             float* __restrict__ e0, float* __restrict__ e1, float* __restrict__ e2)
{
    constexpr int BM = 128, BN = 128, BK = 16;
    __shared__ uint32_t As[BM][20];    // [m][k], pad 16->20: frag reads conflict-free
    __shared__ uint32_t Bs[BK][136];   // [k][n], pad 128->136: frag reads conflict-free

    const int tid  = threadIdx.x;
    const int wid  = tid >> 5;
    const int lane = tid & 31;
    const int wm   = (wid & 3) * 32;   // warp m offset in CTA tile
    const int wn   = (wid >> 2) * 64;  // warp n offset
    const int row  = lane >> 2;        // 0..7
    const int col  = lane & 3;         // 0..3
    const int cCol = blockIdx.x, cRow = blockIdx.y;

    const float* Abase = A  + (size_t)cRow * BM * K;
    const float* Bbase = Bm + (size_t)cCol * BN;

    // per-thread global-load coordinates (2 float4 each for A and B)
    const int ar0 = tid >> 2;              // 0..63
    const int ar1 = ar0 + 64;              // 64..127
    const int ac  = (tid & 3) * 4;         // 0,4,8,12
    const int bk0 = tid >> 5;              // 0..7
    const int bk1 = bk0 + 8;               // 8..15
    const int bn  = (tid & 31) * 4;        // 0..124

    float acc[2][8][4];
    #pragma unroll
    for (int mt = 0; mt < 2; mt++)
        #pragma unroll
        for (int nt = 0; nt < 8; nt++)
            #pragma unroll
            for (int i = 0; i < 4; i++) acc[mt][nt][i] = 0.f;

    const int NT = K / BK;

    // initial tile -> smem
    {
        const float4 a0 = *(const float4*)(Abase + (size_t)ar0 * K + ac);
        const float4 a1 = *(const float4*)(Abase + (size_t)ar1 * K + ac);
        const float4 b0 = *(const float4*)(Bbase + (size_t)bk0 * N + bn);
        const float4 b1 = *(const float4*)(Bbase + (size_t)bk1 * N + bn);
        *(uint4*)&As[ar0][ac] = tf32x4(a0);
        *(uint4*)&As[ar1][ac] = tf32x4(a1);
        *(uint4*)&Bs[bk0][bn] = tf32x4(b0);
        *(uint4*)&Bs[bk1][bn] = tf32x4(b1);
    }
    __syncthreads();

    for (int t = 0; t < NT; t++) {
        float4 pa0, pa1, pb0, pb1;
        if (t + 1 < NT) {
            const int k0 = (t + 1) * BK;
            pa0 = *(const float4*)(Abase + (size_t)ar0 * K + k0 + ac);
            pa1 = *(const float4*)(Abase + (size_t)ar1 * K + k0 + ac);
            pb0 = *(const float4*)(Bbase + (size_t)(k0 + bk0) * N + bn);
            pb1 = *(const float4*)(Bbase + (size_t)(k0 + bk1) * N + bn);
        }

        // compute this tile: 2 k-steps of 8
        #pragma unroll
        for (int ks = 0; ks < BK; ks += 8) {
            uint32_t af[2][4], bf[8][2];
            #pragma unroll
            for (int mt = 0; mt < 2; mt++) {
                af[mt][0] = As[wm + mt * 16 + row    ][ks + col    ];
                af[mt][1] = As[wm + mt * 16 + row + 8][ks + col    ];
                af[mt][2] = As[wm + mt * 16 + row    ][ks + col + 4];
                af[mt][3] = As[wm + mt * 16 + row + 8][ks + col + 4];
            }
            #pragma unroll
            for (int nt = 0; nt < 8; nt++) {
                bf[nt][0] = Bs[ks + col    ][wn + nt * 8 + row];
                bf[nt][1] = Bs[ks + col + 4][wn + nt * 8 + row];
            }
            #pragma unroll
            for (int mt = 0; mt < 2; mt++)
                #pragma unroll
                for (int nt = 0; nt < 8; nt++)
                    MMA_TF32(acc[mt][nt], af[mt], bf[nt]);
        }
        __syncthreads();

        if (t + 1 < NT) {
            *(uint4*)&As[ar0][ac] = tf32x4(pa0);
            *(uint4*)&As[ar1][ac] = tf32x4(pa1);
            *(uint4*)&Bs[bk0][bn] = tf32x4(pb0);
            *(uint4*)&Bs[bk1][bn] = tf32x4(pb1);
            __syncthreads();
        }
    }

    // epilogue
    #pragma unroll
    for (int mt = 0; mt < 2; mt++) {
        const int m0 = cRow * BM + wm + mt * 16 + row;
        #pragma unroll
        for (int nt = 0; nt < 8; nt++) {
            const int n0 = cCol * BN + wn + nt * 8 + col * 2;
            epi_store<EPI>(m0,     n0, make_float2(acc[mt][nt][0], acc[mt][nt][1]),
                           N, bias, resid, C, e0, e1, e2);
            epi_store<EPI>(m0 + 8, n0, make_float2(acc[mt][nt][2], acc[mt][nt][3]),
                           N, bias, resid, C, e0, e1, e2);
        }
    }
}

// ---------------------------------------------------------------------------
// Flash attention (fp32). One thread owns one q row (HD=64 in registers).
// ---------------------------------------------------------------------------
#define KT 16

__global__ __launch_bounds__(128)
void attn_k(const float* __restrict__ q, const float* __restrict__ k,
            const float* __restrict__ v, float* __restrict__ out)
{
    const int bh   = blockIdx.y;
    const int b    = bh >> 4;
    const int h    = bh & 15;
    const int qrow = blockIdx.x * 128 + threadIdx.x;

    __shared__ float Ks[KT][HD_];
    __shared__ float Vs[KT][HD_];

    float qr[HD_];
    {
        const float* qp = q + ((size_t)bh * L_ + qrow) * HD_;
        #pragma unroll
        for (int d = 0; d < HD_; d += 4) {
            const float4 t = *(const float4*)(qp + d);
            qr[d + 0] = t.x * 0.125f;
            qr[d + 1] = t.y * 0.125f;
            qr[d + 2] = t.z * 0.125f;
            qr[d + 3] = t.w * 0.125f;
        }
    }

    float o[HD_];
    #pragma unroll
    for (int d = 0; d < HD_; d++) o[d] = 0.f;
    float mrun = -1e30f, lsum = 0.f;

    const float* kbase = k + (size_t)bh * L_ * HD_;
    const float* vbase = v + (size_t)bh * L_ * HD_;

    for (int t0 = 0; t0 < L_; t0 += KT) {
        {
            const int fi = (int)threadIdx.x;
            #pragma unroll
            for (int i = 0; i < 2; i++) {
                const int idx = i * 128 + fi;
                const int r = idx >> 4, c = (idx & 15) * 4;
                *(float4*)&Ks[r][c] = *(const float4*)(kbase + (size_t)t0 * HD_ + idx * 4);
                *(float4*)&Vs[r][c] = *(const float4*)(vbase + (size_t)t0 * HD_ + idx * 4);
            }
        }
        __syncthreads();

        float s[KT];
        float tmax = mrun;
        #pragma unroll
        for (int j = 0; j < KT; j++) {
            float a0 = 0.f, a1 = 0.f, a2 = 0.f, a3 = 0.f;
            #pragma unroll
            for (int d = 0; d < HD_; d += 4) {
                const float4 kv = *(const float4*)&Ks[j][d];
                a0 += qr[d + 0] * kv.x;
                a1 += qr[d + 1] * kv.y;
                a2 += qr[d + 2] * kv.z;
                a3 += qr[d + 3] * kv.w;
            }
            const float sj = (a0 + a1) + (a2 + a3);
            s[j] = sj;
            tmax = fmaxf(tmax, sj);
        }

        const float corr = __expf(mrun - tmax);
        lsum *= corr;
        #pragma unroll
        for (int d = 0; d < HD_; d++) o[d] *= corr;

        #pragma unroll
        for (int j = 0; j < KT; j++) {
            const float p = __expf(s[j] - tmax);
            lsum += p;
            #pragma unroll
            for (int d = 0; d < HD_; d += 4) {
                const float4 vv = *(const float4*)&Vs[j][d];
                o[d + 0] += p * vv.x;
                o[d + 1] += p * vv.y;
                o[d + 2] += p * vv.z;
                o[d + 3] += p * vv.w;
            }
        }
        mrun = tmax;
        __syncthreads();
    }

    const float inv = 1.f / lsum;
    float* op = out + ((size_t)qrow * B_ + b) * D_ + h * HD_;
    #pragma unroll
    for (int d = 0; d < HD_; d += 4) {
        float4 t;
        t.x = o[d + 0] * inv;
        t.y = o[d + 1] * inv;
        t.z = o[d + 2] * inv;
        t.w = o[d + 3] * inv;
        *(float4*)(op + d) = t;
    }
}

// ---------------------------------------------------------------------------
// Launch
// ---------------------------------------------------------------------------
extern "C" void kernel_launch(void* const* d_in, const int* in_sizes, int n_in,
                              void* d_out, int out_size)
{
    const float* x      = (const float*)d_in[0];
    const float* ln1_g  = (const float*)d_in[1];
    const float* ln1_b  = (const float*)d_in[2];
    const float* w_attn = (const float*)d_in[3];
    const float* b_attn = (const float*)d_in[4];
    const float* w_proj = (const float*)d_in[5];
    const float* b_proj = (const float*)d_in[6];
    const float* ln2_g  = (const float*)d_in[7];
    const float* ln2_b  = (const float*)d_in[8];
    const float* w_fc   = (const float*)d_in[9];
    const float* b_fc   = (const float*)d_in[10];
    const float* w_out  = (const float*)d_in[11];
    const float* b_out  = (const float*)d_in[12];

    float* out  = (float*)d_out;
    float* kout = out  + (size_t)L_ * B_ * D_;                 // present[0]
    float* vout = kout + (size_t)B_ * H_ * L_ * HD_;           // present[1]

    float *hptr, *qptr, *atptr, *x1ptr, *mptr;
    cudaGetSymbolAddress((void**)&hptr,  g_h);
    cudaGetSymbolAddress((void**)&qptr,  g_q);
    cudaGetSymbolAddress((void**)&atptr, g_at);
    cudaGetSymbolAddress((void**)&x1ptr, g_x1);
    cudaGetSymbolAddress((void**)&mptr,  g_m);

    // 1) LN1
    ln_k<<<MTOK, 256>>>(x, ln1_g, ln1_b, hptr);

    // 2) QKV GEMM [4096,1024]@[1024,3072]; scatter q->scratch, k/v->present
    mgemm_k<0><<<dim3(3 * D_ / 128, MTOK / 128), 256>>>(
        hptr, w_attn, b_attn, nullptr, nullptr, MTOK, 3 * D_, D_,
        qptr, kout, vout);

    // 3) attention -> token-major a
    attn_k<<<dim3(L_ / 128, B_ * H_), 128>>>(qptr, kout, vout, atptr);

    // 4) proj + residual -> x1
    mgemm_k<1><<<dim3(D_ / 128, MTOK / 128), 256>>>(
        atptr, w_proj, b_proj, x, x1ptr, MTOK, D_, D_,
        nullptr, nullptr, nullptr);

    // 5) LN2
    ln_k<<<MTOK, 256>>>(x1ptr, ln2_g, ln2_b, hptr);

    // 6) FC + GELU
    mgemm_k<2><<<dim3(DFF_ / 128, MTOK / 128), 256>>>(
        hptr, w_fc, b_fc, nullptr, mptr, MTOK, DFF_, D_,
        nullptr, nullptr, nullptr);

    // 7) out proj + residual -> final x
    mgemm_k<1><<<dim3(D_ / 128, MTOK / 128), 256>>>(
        mptr, w_out, b_out, x1ptr, out, MTOK, D_, DFF_,
        nullptr, nullptr, nullptr);
}

// round 4
// speedup vs baseline: 3.4701x; 2.0179x over previous
#include <cuda_runtime.h>
#include <math.h>
#include <stdint.h>

// Problem dims (fixed)
#define L_    2048
#define B_    2
#define D_    1024
#define H_    16
#define HD_   64
#define DFF_  4096
#define MTOK  4096   // L*B tokens

// ---------------------------------------------------------------------------
// Scratch (static device globals; allocation inside kernel_launch is banned)
// ---------------------------------------------------------------------------
__device__ float g_h [(size_t)MTOK * D_];    // LN output (reused for LN1 and LN2)
__device__ float g_q [(size_t)B_ * H_ * L_ * HD_];
__device__ float g_at[(size_t)MTOK * D_];    // attention output, token-major
__device__ float g_x1[(size_t)MTOK * D_];    // x + attn (residual 1)
__device__ float g_m [(size_t)MTOK * DFF_];  // gelu(fc) activations

// ---------------------------------------------------------------------------
// tf32 helpers (baseline PTX only — no tcgen05 on this build)
// ---------------------------------------------------------------------------
__device__ __forceinline__ uint32_t tf32r(float f) {
    uint32_t r;
    asm("cvt.rna.tf32.f32 %0, %1;" : "=r"(r) : "f"(f));
    return r;
}
__device__ __forceinline__ uint4 tf32x4(float4 v) {
    return make_uint4(tf32r(v.x), tf32r(v.y), tf32r(v.z), tf32r(v.w));
}
__device__ __forceinline__ float ex2f(float x) {
    float y;
    asm("ex2.approx.f32 %0, %1;" : "=f"(y) : "f"(x));
    return y;
}
__device__ __forceinline__ uint32_t smem_u32(const void* p) {
    uint32_t a;
    asm("{ .reg .u64 t; cvta.to.shared.u64 t, %1; cvt.u32.u64 %0, t; }"
        : "=r"(a) : "l"(p));
    return a;
}
__device__ __forceinline__ void cpa16(uint32_t dst, const void* src) {
    asm volatile("cp.async.cg.shared.global [%0], [%1], 16;"
                 :: "r"(dst), "l"(src));
}

#define MMA_TF32(d, a, b)                                                   \
    asm volatile(                                                           \
        "mma.sync.aligned.m16n8k8.row.col.f32.tf32.tf32.f32 "               \
        "{%0,%1,%2,%3}, {%4,%5,%6,%7}, {%8,%9}, {%0,%1,%2,%3};"             \
        : "+f"((d)[0]), "+f"((d)[1]), "+f"((d)[2]), "+f"((d)[3])            \
        : "r"((a)[0]), "r"((a)[1]), "r"((a)[2]), "r"((a)[3]),               \
          "r"((b)[0]), "r"((b)[1]))

// ---------------------------------------------------------------------------
// LayerNorm: one block per token row (1024 elems), 256 threads * float4
// ---------------------------------------------------------------------------
__global__ __launch_bounds__(256)
void ln_k(const float* __restrict__ x, const float* __restrict__ g,
          const float* __restrict__ b, float* __restrict__ out)
{
    const int row = blockIdx.x;
    const int tid = threadIdx.x;
    const float4 v = *(const float4*)(x + (size_t)row * D_ + tid * 4);

    float s = v.x + v.y + v.z + v.w;
    float q = v.x * v.x + v.y * v.y + v.z * v.z + v.w * v.w;
    #pragma unroll
    for (int o = 16; o > 0; o >>= 1) {
        s += __shfl_down_sync(0xffffffffu, s, o);
        q += __shfl_down_sync(0xffffffffu, q, o);
    }
    __shared__ float ss[8], sq[8];
    const int w = tid >> 5, ln = tid & 31;
    if (ln == 0) { ss[w] = s; sq[w] = q; }
    __syncthreads();
    float S = 0.f, Q = 0.f;
    #pragma unroll
    for (int i = 0; i < 8; i++) { S += ss[i]; Q += sq[i]; }

    const float mu  = S * (1.f / D_);
    const float var = Q * (1.f / D_) - mu * mu;
    const float rs  = rsqrtf(var + 1e-5f);

    const float4 gv = *(const float4*)(g + tid * 4);
    const float4 bv = *(const float4*)(b + tid * 4);
    float4 o;
    o.x = (v.x - mu) * rs * gv.x + bv.x;
    o.y = (v.y - mu) * rs * gv.y + bv.y;
    o.z = (v.z - mu) * rs * gv.z + bv.z;
    o.w = (v.w - mu) * rs * gv.w + bv.w;
    *(float4*)(out + (size_t)row * D_ + tid * 4) = o;
}

// ---------------------------------------------------------------------------
// Epilogue helper: consume one float2 at (m, n), n even.
// ---------------------------------------------------------------------------
template <int EPI>
__device__ __forceinline__ void epi_store(
    int m, int n, float2 v, int N,
    const float* __restrict__ bias, const float* __restrict__ resid,
    float* __restrict__ C,
    float* __restrict__ e0, float* __restrict__ e1, float* __restrict__ e2)
{
    const float2 bv = *(const float2*)(bias + n);
    v.x += bv.x;
    v.y += bv.y;
    if (EPI == 0) {
        const int part = n >> 10;
        const int d    = n & 1023;
        const int hh   = d >> 6;
        const int hd   = d & 63;
        const int l    = m >> 1;     // token m = l*B + b, B=2
        const int bb   = m & 1;
        const size_t idx = (((size_t)(bb * H_ + hh) * L_) + l) * HD_ + hd;
        float* dst = (part == 0) ? e0 : (part == 1) ? e1 : e2;
        *(float2*)(dst + idx) = v;
    } else if (EPI == 1) {
        const size_t idx = (size_t)m * N + n;
        const float2 rv = *(const float2*)(resid + idx);
        v.x += rv.x;
        v.y += rv.y;
        *(float2*)(C + idx) = v;
    } else {
        float2 o;
        const float t0 = tanhf(0.7978845608028654f *
                               (v.x + 0.044715f * v.x * v.x * v.x));
        o.x = 0.5f * v.x * (1.f + t0);
        const float t1 = tanhf(0.7978845608028654f *
                               (v.y + 0.044715f * v.y * v.y * v.y));
        o.y = 0.5f * v.y * (1.f + t1);
        *(float2*)(C + (size_t)m * N + n) = o;
    }
}

// ---------------------------------------------------------------------------
// tf32 mma.sync GEMM: C[M,N] = A[M,K] @ B[K,N] (+bias, fused epilogue).
// CTA 128x128, BK=16, 256 threads (8 warps, 4x2 grid, warp tile 32x64).
// ---------------------------------------------------------------------------
template <int EPI>
__global__ __launch_bounds__(256, 2)
void mgemm_k(const float* __restrict__ A, const float* __restrict__ Bm,
             const float* __restrict__ bias, const float* __restrict__ resid,
             float* __restrict__ C, int M, int N, int K,
             float* __restrict__ e0, float* __restrict__ e1, float* __restrict__ e2)
{
    constexpr int BM = 128, BN = 128, BK = 16;
    __shared__ uint32_t As[BM][20];
    __shared__ uint32_t Bs[BK][136];

    const int tid  = threadIdx.x;
    const int wid  = tid >> 5;
    const int lane = tid & 31;
    const int wm   = (wid & 3) * 32;
    const int wn   = (wid >> 2) * 64;
    const int row  = lane >> 2;
    const int col  = lane & 3;
    const int cCol = blockIdx.x, cRow = blockIdx.y;

    const float* Abase = A  + (size_t)cRow * BM * K;
    const float* Bbase = Bm + (size_t)cCol * BN;

    const int ar0 = tid >> 2;
    const int ar1 = ar0 + 64;
    const int ac  = (tid & 3) * 4;
    const int bk0 = tid >> 5;
    const int bk1 = bk0 + 8;
    const int bn  = (tid & 31) * 4;

    float acc[2][8][4];
    #pragma unroll
    for (int mt = 0; mt < 2; mt++)
        #pragma unroll
        for (int nt = 0; nt < 8; nt++)
            #pragma unroll
            for (int i = 0; i < 4; i++) acc[mt][nt][i] = 0.f;

    const int NT = K / BK;

    {
        const float4 a0 = *(const float4*)(Abase + (size_t)ar0 * K + ac);
        const float4 a1 = *(const float4*)(Abase + (size_t)ar1 * K + ac);
        const float4 b0 = *(const float4*)(Bbase + (size_t)bk0 * N + bn);
        const float4 b1 = *(const float4*)(Bbase + (size_t)bk1 * N + bn);
        *(uint4*)&As[ar0][ac] = tf32x4(a0);
        *(uint4*)&As[ar1][ac] = tf32x4(a1);
        *(uint4*)&Bs[bk0][bn] = tf32x4(b0);
        *(uint4*)&Bs[bk1][bn] = tf32x4(b1);
    }
    __syncthreads();

    for (int t = 0; t < NT; t++) {
        float4 pa0, pa1, pb0, pb1;
        if (t + 1 < NT) {
            const int k0 = (t + 1) * BK;
            pa0 = *(const float4*)(Abase + (size_t)ar0 * K + k0 + ac);
            pa1 = *(const float4*)(Abase + (size_t)ar1 * K + k0 + ac);
            pb0 = *(const float4*)(Bbase + (size_t)(k0 + bk0) * N + bn);
            pb1 = *(const float4*)(Bbase + (size_t)(k0 + bk1) * N + bn);
        }

        #pragma unroll
        for (int ks = 0; ks < BK; ks += 8) {
            uint32_t af[2][4], bf[8][2];
            #pragma unroll
            for (int mt = 0; mt < 2; mt++) {
                af[mt][0] = As[wm + mt * 16 + row    ][ks + col    ];
                af[mt][1] = As[wm + mt * 16 + row + 8][ks + col    ];
                af[mt][2] = As[wm + mt * 16 + row    ][ks + col + 4];
                af[mt][3] = As[wm + mt * 16 + row + 8][ks + col + 4];
            }
            #pragma unroll
            for (int nt = 0; nt < 8; nt++) {
                bf[nt][0] = Bs[ks + col    ][wn + nt * 8 + row];
                bf[nt][1] = Bs[ks + col + 4][wn + nt * 8 + row];
            }
            #pragma unroll
            for (int mt = 0; mt < 2; mt++)
                #pragma unroll
                for (int nt = 0; nt < 8; nt++)
                    MMA_TF32(acc[mt][nt], af[mt], bf[nt]);
        }
        __syncthreads();

        if (t + 1 < NT) {
            *(uint4*)&As[ar0][ac] = tf32x4(pa0);
            *(uint4*)&As[ar1][ac] = tf32x4(pa1);
            *(uint4*)&Bs[bk0][bn] = tf32x4(pb0);
            *(uint4*)&Bs[bk1][bn] = tf32x4(pb1);
            __syncthreads();
        }
    }

    #pragma unroll
    for (int mt = 0; mt < 2; mt++) {
        const int m0 = cRow * BM + wm + mt * 16 + row;
        #pragma unroll
        for (int nt = 0; nt < 8; nt++) {
            const int n0 = cCol * BN + wn + nt * 8 + col * 2;
            epi_store<EPI>(m0,     n0, make_float2(acc[mt][nt][0], acc[mt][nt][1]),
                           N, bias, resid, C, e0, e1, e2);
            epi_store<EPI>(m0 + 8, n0, make_float2(acc[mt][nt][2], acc[mt][nt][3]),
                           N, bias, resid, C, e0, e1, e2);
        }
    }
}

// ---------------------------------------------------------------------------
// Tensor-core flash attention (tf32 mma.sync).
// CTA: 128 q-rows x one (b,h). 8 warps, warp = 16 q-rows, Q frags in regs.
// KV tiles of 32 rows, double-buffered via cp.async.
// Smem strides: Ks 68 (bank = 4r+c unique), Vs 72 (bank = 8c+r unique).
// grid = (L/128, B*H), block = 256.
// ---------------------------------------------------------------------------
#define KVT 32
#define NTILES (L_ / KVT)

__global__ __launch_bounds__(256, 2)
void attn_mma_k(const float* __restrict__ q, const float* __restrict__ k,
                const float* __restrict__ v, float* __restrict__ out)
{
    __shared__ float Ks[2][KVT][68];
    __shared__ float Vs[2][KVT][72];

    const int bh   = blockIdx.y;
    const int b    = bh >> 4;
    const int h    = bh & 15;
    const int tid  = threadIdx.x;
    const int wid  = tid >> 5;
    const int lane = tid & 31;
    const int gid  = lane >> 2;    // row in fragment
    const int tg   = lane & 3;     // col group

    const float* kbase = k + (size_t)bh * L_ * HD_;
    const float* vbase = v + (size_t)bh * L_ * HD_;

    // per-thread cp.async coordinates: 2 chunks each for K and V per tile
    const int ld_row0 = tid >> 4;            // 0..15
    const int ld_row1 = ld_row0 + 16;        // 16..31
    const int ld_c    = (tid & 15) * 4;      // float offset (16B chunks)
    const uint32_t sK0 = smem_u32(&Ks[0][0][0]);
    const uint32_t sV0 = smem_u32(&Vs[0][0][0]);

    // Q fragments in registers (scaled by log2(e)/sqrt(HD))
    const int qr = blockIdx.x * 128 + wid * 16 + gid;
    const float* qp = q + (size_t)bh * L_ * HD_;
    const float SC = 0.18033688011112042f;  // log2(e) / 8
    uint32_t qf[8][4];
    #pragma unroll
    for (int kq = 0; kq < 8; kq++) {
        qf[kq][0] = __float_as_uint(qp[(size_t)qr      * HD_ + 8 * kq + tg    ] * SC);
        qf[kq][1] = __float_as_uint(qp[(size_t)(qr + 8) * HD_ + 8 * kq + tg    ] * SC);
        qf[kq][2] = __float_as_uint(qp[(size_t)qr      * HD_ + 8 * kq + tg + 4] * SC);
        qf[kq][3] = __float_as_uint(qp[(size_t)(qr + 8) * HD_ + 8 * kq + tg + 4] * SC);
    }

    float oacc[8][4];
    #pragma unroll
    for (int on = 0; on < 8; on++)
        #pragma unroll
        for (int i = 0; i < 4; i++) oacc[on][i] = 0.f;
    float mr0 = -1e30f, mr1 = -1e30f, ls0 = 0.f, ls1 = 0.f;

    // prologue: tile 0 -> buffer 0
    {
        const float* ksrc = kbase;
        const float* vsrc = vbase;
        cpa16(sK0 + (ld_row0 * 68 + ld_c) * 4, ksrc + (size_t)ld_row0 * HD_ + ld_c);
        cpa16(sK0 + (ld_row1 * 68 + ld_c) * 4, ksrc + (size_t)ld_row1 * HD_ + ld_c);
        cpa16(sV0 + (ld_row0 * 72 + ld_c) * 4, vsrc + (size_t)ld_row0 * HD_ + ld_c);
        cpa16(sV0 + (ld_row1 * 72 + ld_c) * 4, vsrc + (size_t)ld_row1 * HD_ + ld_c);
        asm volatile("cp.async.commit_group;");
    }

    for (int t = 0; t < NTILES; t++) {
        const int cur = t & 1;
        if (t + 1 < NTILES) {
            const int nb = (t + 1) & 1;
            const float* ksrc = kbase + (size_t)(t + 1) * KVT * HD_;
            const float* vsrc = vbase + (size_t)(t + 1) * KVT * HD_;
            const uint32_t dK = sK0 + nb * (KVT * 68 * 4);
            const uint32_t dV = sV0 + nb * (KVT * 72 * 4);
            cpa16(dK + (ld_row0 * 68 + ld_c) * 4, ksrc + (size_t)ld_row0 * HD_ + ld_c);
            cpa16(dK + (ld_row1 * 68 + ld_c) * 4, ksrc + (size_t)ld_row1 * HD_ + ld_c);
            cpa16(dV + (ld_row0 * 72 + ld_c) * 4, vsrc + (size_t)ld_row0 * HD_ + ld_c);
            cpa16(dV + (ld_row1 * 72 + ld_c) * 4, vsrc + (size_t)ld_row1 * HD_ + ld_c);
            asm volatile("cp.async.commit_group;");
            asm volatile("cp.async.wait_group 1;");
        } else {
            asm volatile("cp.async.wait_group 0;");
        }
        __syncthreads();

        // ---- S = Q @ K^T for this warp's 16 rows x 32 kv cols ----
        float sacc[4][4];
        #pragma unroll
        for (int nt = 0; nt < 4; nt++)
            #pragma unroll
            for (int i = 0; i < 4; i++) sacc[nt][i] = 0.f;

        #pragma unroll
        for (int kq = 0; kq < 8; kq++) {
            uint32_t bf[4][2];
            #pragma unroll
            for (int nt = 0; nt < 4; nt++) {
                bf[nt][0] = *(const uint32_t*)&Ks[cur][nt * 8 + gid][8 * kq + tg    ];
                bf[nt][1] = *(const uint32_t*)&Ks[cur][nt * 8 + gid][8 * kq + tg + 4];
            }
            #pragma unroll
            for (int nt = 0; nt < 4; nt++)
                MMA_TF32(sacc[nt], qf[kq], bf[nt]);
        }

        // ---- online softmax (base-2; scale folded into Q) ----
        float m0 = mr0, m1 = mr1;
        #pragma unroll
        for (int nt = 0; nt < 4; nt++) {
            m0 = fmaxf(m0, fmaxf(sacc[nt][0], sacc[nt][1]));
            m1 = fmaxf(m1, fmaxf(sacc[nt][2], sacc[nt][3]));
        }
        m0 = fmaxf(m0, __shfl_xor_sync(0xffffffffu, m0, 1));
        m0 = fmaxf(m0, __shfl_xor_sync(0xffffffffu, m0, 2));
        m1 = fmaxf(m1, __shfl_xor_sync(0xffffffffu, m1, 1));
        m1 = fmaxf(m1, __shfl_xor_sync(0xffffffffu, m1, 2));

        const float sc0 = ex2f(mr0 - m0);
        const float sc1 = ex2f(mr1 - m1);
        mr0 = m0; mr1 = m1;

        float rs0 = 0.f, rs1 = 0.f;
        #pragma unroll
        for (int nt = 0; nt < 4; nt++) {
            sacc[nt][0] = ex2f(sacc[nt][0] - m0);
            sacc[nt][1] = ex2f(sacc[nt][1] - m0);
            sacc[nt][2] = ex2f(sacc[nt][2] - m1);
            sacc[nt][3] = ex2f(sacc[nt][3] - m1);
            rs0 += sacc[nt][0] + sacc[nt][1];
            rs1 += sacc[nt][2] + sacc[nt][3];
        }
        rs0 += __shfl_xor_sync(0xffffffffu, rs0, 1);
        rs0 += __shfl_xor_sync(0xffffffffu, rs0, 2);
        rs1 += __shfl_xor_sync(0xffffffffu, rs1, 1);
        rs1 += __shfl_xor_sync(0xffffffffu, rs1, 2);
        ls0 = ls0 * sc0 + rs0;
        ls1 = ls1 * sc1 + rs1;

        #pragma unroll
        for (int on = 0; on < 8; on++) {
            oacc[on][0] *= sc0;
            oacc[on][1] *= sc0;
            oacc[on][2] *= sc1;
            oacc[on][3] *= sc1;
        }

        // ---- O += P @ V : per kv-kstep, shuffle C-frag cols -> A-frag ----
        const int base = lane & ~3;
        const int src0 = base + (tg >> 1);
        const int src2 = src0 + 2;
        #pragma unroll
        for (int kb = 0; kb < 4; kb++) {
            uint32_t af[4];
            {
                float x, y;
                x = __shfl_sync(0xffffffffu, sacc[kb][0], src0);
                y = __shfl_sync(0xffffffffu, sacc[kb][1], src0);
                af[0] = __float_as_uint((tg & 1) ? y : x);
                x = __shfl_sync(0xffffffffu, sacc[kb][2], src0);
                y = __shfl_sync(0xffffffffu, sacc[kb][3], src0);
                af[1] = __float_as_uint((tg & 1) ? y : x);
                x = __shfl_sync(0xffffffffu, sacc[kb][0], src2);
                y = __shfl_sync(0xffffffffu, sacc[kb][1], src2);
                af[2] = __float_as_uint((tg & 1) ? y : x);
                x = __shfl_sync(0xffffffffu, sacc[kb][2], src2);
                y = __shfl_sync(0xffffffffu, sacc[kb][3], src2);
                af[3] = __float_as_uint((tg & 1) ? y : x);
            }
            #pragma unroll
            for (int on = 0; on < 8; on++) {
                uint32_t bv[2];
                bv[0] = *(const uint32_t*)&Vs[cur][kb * 8 + tg    ][on * 8 + gid];
                bv[1] = *(const uint32_t*)&Vs[cur][kb * 8 + tg + 4][on * 8 + gid];
                MMA_TF32(oacc[on], af, bv);
            }
        }
        __syncthreads();
    }

    // ---- normalize + write token-major [l*B + b][h*64 + hd] ----
    const float inv0 = 1.f / ls0;
    const float inv1 = 1.f / ls1;
    float* op0 = out + ((size_t)qr       * B_ + b) * D_ + h * HD_;
    float* op1 = out + ((size_t)(qr + 8) * B_ + b) * D_ + h * HD_;
    #pragma unroll
    for (int on = 0; on < 8; on++) {
        const int c0 = on * 8 + tg * 2;
        *(float2*)(op0 + c0) = make_float2(oacc[on][0] * inv0, oacc[on][1] * inv0);
        *(float2*)(op1 + c0) = make_float2(oacc[on][2] * inv1, oacc[on][3] * inv1);
    }
}

// ---------------------------------------------------------------------------
// Launch
// ---------------------------------------------------------------------------
extern "C" void kernel_launch(void* const* d_in, const int* in_sizes, int n_in,
                              void* d_out, int out_size)
{
    const float* x      = (const float*)d_in[0];
    const float* ln1_g  = (const float*)d_in[1];
    const float* ln1_b  = (const float*)d_in[2];
    const float* w_attn = (const float*)d_in[3];
    const float* b_attn = (const float*)d_in[4];
    const float* w_proj = (const float*)d_in[5];
    const float* b_proj = (const float*)d_in[6];
    const float* ln2_g  = (const float*)d_in[7];
    const float* ln2_b  = (const float*)d_in[8];
    const float* w_fc   = (const float*)d_in[9];
    const float* b_fc   = (const float*)d_in[10];
    const float* w_out  = (const float*)d_in[11];
    const float* b_out  = (const float*)d_in[12];

    float* out  = (float*)d_out;
    float* kout = out  + (size_t)L_ * B_ * D_;                 // present[0]
    float* vout = kout + (size_t)B_ * H_ * L_ * HD_;           // present[1]

    float *hptr, *qptr, *atptr, *x1ptr, *mptr;
    cudaGetSymbolAddress((void**)&hptr,  g_h);
    cudaGetSymbolAddress((void**)&qptr,  g_q);
    cudaGetSymbolAddress((void**)&atptr, g_at);
    cudaGetSymbolAddress((void**)&x1ptr, g_x1);
    cudaGetSymbolAddress((void**)&mptr,  g_m);

    // 1) LN1
    ln_k<<<MTOK, 256>>>(x, ln1_g, ln1_b, hptr);

    // 2) QKV GEMM [4096,1024]@[1024,3072]; scatter q->scratch, k/v->present
    mgemm_k<0><<<dim3(3 * D_ / 128, MTOK / 128), 256>>>(
        hptr, w_attn, b_attn, nullptr, nullptr, MTOK, 3 * D_, D_,
        qptr, kout, vout);

    // 3) tensor-core attention -> token-major a
    attn_mma_k<<<dim3(L_ / 128, B_ * H_), 256>>>(qptr, kout, vout, atptr);

    // 4) proj + residual -> x1
    mgemm_k<1><<<dim3(D_ / 128, MTOK / 128), 256>>>(
        atptr, w_proj, b_proj, x, x1ptr, MTOK, D_, D_,
        nullptr, nullptr, nullptr);

    // 5) LN2
    ln_k<<<MTOK, 256>>>(x1ptr, ln2_g, ln2_b, hptr);

    // 6) FC + GELU
    mgemm_k<2><<<dim3(DFF_ / 128, MTOK / 128), 256>>>(
        hptr, w_fc, b_fc, nullptr, mptr, MTOK, DFF_, D_,
        nullptr, nullptr, nullptr);

    // 7) out proj + residual -> final x
    mgemm_k<1><<<dim3(D_ / 128, MTOK / 128), 256>>>(
        mptr, w_out, b_out, x1ptr, out, MTOK, D_, DFF_,
        nullptr, nullptr, nullptr);
}

// round 5
// speedup vs baseline: 4.3408x; 1.2509x over previous
#include <cuda_runtime.h>
#include <math.h>
#include <stdint.h>

// Problem dims (fixed)
#define L_    2048
#define B_    2
#define D_    1024
#define H_    16
#define HD_   64
#define DFF_  4096
#define MTOK  4096   // L*B tokens

// ---------------------------------------------------------------------------
// Scratch (static device globals; allocation inside kernel_launch is banned)
// ---------------------------------------------------------------------------
__device__ float g_h [(size_t)MTOK * D_];    // LN output (reused for LN1 and LN2)
__device__ float g_q [(size_t)B_ * H_ * L_ * HD_];
__device__ float g_at[(size_t)MTOK * D_];    // attention output, token-major
__device__ float g_x1[(size_t)MTOK * D_];    // x + attn (residual 1)
__device__ float g_m [(size_t)MTOK * DFF_];  // gelu(fc) activations

// ---------------------------------------------------------------------------
// helpers (baseline PTX only — no tcgen05 on this compute_103 build)
// ---------------------------------------------------------------------------
__device__ __forceinline__ float ex2f(float x) {
    float y;
    asm("ex2.approx.f32 %0, %1;" : "=f"(y) : "f"(x));
    return y;
}
__device__ __forceinline__ uint32_t smem_u32(const void* p) {
    uint32_t a;
    asm("{ .reg .u64 t; cvta.to.shared.u64 t, %1; cvt.u32.u64 %0, t; }"
        : "=r"(a) : "l"(p));
    return a;
}
__device__ __forceinline__ void cpa16(uint32_t dst, const void* src) {
    asm volatile("cp.async.cg.shared.global [%0], [%1], 16;"
                 :: "r"(dst), "l"(src));
}
// pack two f32 -> f16x2 {lo, hi} (PTX: first source = high half)
__device__ __forceinline__ uint32_t pkh(float lo, float hi) {
    uint32_t r;
    asm("cvt.rn.f16x2.f32 %0, %1, %2;" : "=r"(r) : "f"(hi), "f"(lo));
    return r;
}

#define MMA_F16(d, a, b)                                                    \
    asm volatile(                                                           \
        "mma.sync.aligned.m16n8k16.row.col.f32.f16.f16.f32 "                \
        "{%0,%1,%2,%3}, {%4,%5,%6,%7}, {%8,%9}, {%0,%1,%2,%3};"             \
        : "+f"((d)[0]), "+f"((d)[1]), "+f"((d)[2]), "+f"((d)[3])            \
        : "r"((a)[0]), "r"((a)[1]), "r"((a)[2]), "r"((a)[3]),               \
          "r"((b)[0]), "r"((b)[1]))

#define MMA_TF32(d, a, b)                                                   \
    asm volatile(                                                           \
        "mma.sync.aligned.m16n8k8.row.col.f32.tf32.tf32.f32 "               \
        "{%0,%1,%2,%3}, {%4,%5,%6,%7}, {%8,%9}, {%0,%1,%2,%3};"             \
        : "+f"((d)[0]), "+f"((d)[1]), "+f"((d)[2]), "+f"((d)[3])            \
        : "r"((a)[0]), "r"((a)[1]), "r"((a)[2]), "r"((a)[3]),               \
          "r"((b)[0]), "r"((b)[1]))

// ---------------------------------------------------------------------------
// LayerNorm: one block per token row (1024 elems), 256 threads * float4
// ---------------------------------------------------------------------------
__global__ __launch_bounds__(256)
void ln_k(const float* __restrict__ x, const float* __restrict__ g,
          const float* __restrict__ b, float* __restrict__ out)
{
    const int row = blockIdx.x;
    const int tid = threadIdx.x;
    const float4 v = *(const float4*)(x + (size_t)row * D_ + tid * 4);

    float s = v.x + v.y + v.z + v.w;
    float q = v.x * v.x + v.y * v.y + v.z * v.z + v.w * v.w;
    #pragma unroll
    for (int o = 16; o > 0; o >>= 1) {
        s += __shfl_down_sync(0xffffffffu, s, o);
        q += __shfl_down_sync(0xffffffffu, q, o);
    }
    __shared__ float ss[8], sq[8];
    const int w = tid >> 5, ln = tid & 31;
    if (ln == 0) { ss[w] = s; sq[w] = q; }
    __syncthreads();
    float S = 0.f, Q = 0.f;
    #pragma unroll
    for (int i = 0; i < 8; i++) { S += ss[i]; Q += sq[i]; }

    const float mu  = S * (1.f / D_);
    const float var = Q * (1.f / D_) - mu * mu;
    const float rs  = rsqrtf(var + 1e-5f);

    const float4 gv = *(const float4*)(g + tid * 4);
    const float4 bv = *(const float4*)(b + tid * 4);
    float4 o;
    o.x = (v.x - mu) * rs * gv.x + bv.x;
    o.y = (v.y - mu) * rs * gv.y + bv.y;
    o.z = (v.z - mu) * rs * gv.z + bv.z;
    o.w = (v.w - mu) * rs * gv.w + bv.w;
    *(float4*)(out + (size_t)row * D_ + tid * 4) = o;
}

// ---------------------------------------------------------------------------
// Epilogue helper: consume one float2 at (m, n), n even.
// ---------------------------------------------------------------------------
template <int EPI>
__device__ __forceinline__ void epi_store(
    int m, int n, float2 v, int N,
    const float* __restrict__ bias, const float* __restrict__ resid,
    float* __restrict__ C,
    float* __restrict__ e0, float* __restrict__ e1, float* __restrict__ e2)
{
    const float2 bv = *(const float2*)(bias + n);
    v.x += bv.x;
    v.y += bv.y;
    if (EPI == 0) {
        const int part = n >> 10;
        const int d    = n & 1023;
        const int hh   = d >> 6;
        const int hd   = d & 63;
        const int l    = m >> 1;     // token m = l*B + b, B=2
        const int bb   = m & 1;
        const size_t idx = (((size_t)(bb * H_ + hh) * L_) + l) * HD_ + hd;
        float* dst = (part == 0) ? e0 : (part == 1) ? e1 : e2;
        *(float2*)(dst + idx) = v;
    } else if (EPI == 1) {
        const size_t idx = (size_t)m * N + n;
        const float2 rv = *(const float2*)(resid + idx);
        v.x += rv.x;
        v.y += rv.y;
        *(float2*)(C + idx) = v;
    } else {
        float2 o;
        const float t0 = tanhf(0.7978845608028654f *
                               (v.x + 0.044715f * v.x * v.x * v.x));
        o.x = 0.5f * v.x * (1.f + t0);
        const float t1 = tanhf(0.7978845608028654f *
                               (v.y + 0.044715f * v.y * v.y * v.y));
        o.y = 0.5f * v.y * (1.f + t1);
        *(float2*)(C + (size_t)m * N + n) = o;
    }
}

// ---------------------------------------------------------------------------
// fp16 m16n8k16 GEMM: C[M,N] = A[M,K] @ B[K,N] (+bias, fused epilogue).
// CTA 128x128, BK=16, 256 threads (8 warps, 4x2, warp tile 32x64).
// Smem holds f16x2 "fragment pairs" so every fragment load is one LDS.64:
//   Asp[row][4] uint2: pair c = {f16x2(A[row][2c,2c+1]), f16x2(A[row][2c+8,2c+9])},
//       stored at index c ^ ((row>>2)&1)  (conflict-free STS.64/LDS.64).
//   Bsp[4][132] uint2 (stride 132 => addr/8 % 16 spreads): pair c at column n =
//       {f16x2(B[2c,2c+1][n]), f16x2(B[2c+8,2c+9][n])}.
// ---------------------------------------------------------------------------
template <int EPI>
__global__ __launch_bounds__(256, 2)
void hgemm_k(const float* __restrict__ A, const float* __restrict__ Bm,
             const float* __restrict__ bias, const float* __restrict__ resid,
             float* __restrict__ C, int M, int N, int K,
             float* __restrict__ e0, float* __restrict__ e1, float* __restrict__ e2)
{
    constexpr int BM = 128, BN = 128, BK = 16;
    __shared__ uint2 Asp[BM * 4];
    __shared__ uint2 Bsp[4 * 132];

    const int tid  = threadIdx.x;
    const int wid  = tid >> 5;
    const int lane = tid & 31;
    const int wm   = (wid & 3) * 32;
    const int wn   = (wid >> 2) * 64;
    const int gid  = lane >> 2;
    const int cB   = lane & 3;
    const int crA  = cB ^ ((lane >> 4) & 1);
    const int cCol = blockIdx.x, cRow = blockIdx.y;

    const float* Abase = A  + (size_t)cRow * BM * K;
    const float* Bbase = Bm + (size_t)cCol * BN;

    // writer coords
    const int row_a  = tid >> 1;          // 0..127
    const int half_a = tid & 1;           // k-quad selector
    const int aswz   = (row_a >> 2) & 1;
    const int n_b    = tid & 127;         // B column
    const int kh_b   = (tid >> 7) * 4;    // k base within tile (0 or 4)

    float acc[2][8][4];
    #pragma unroll
    for (int mt = 0; mt < 2; mt++)
        #pragma unroll
        for (int nt = 0; nt < 8; nt++)
            #pragma unroll
            for (int i = 0; i < 4; i++) acc[mt][nt][i] = 0.f;

    const int NT = K / BK;

    // ---- initial tile -> smem ----
    {
        const float4 alo = *(const float4*)(Abase + (size_t)row_a * K + half_a * 4);
        const float4 ahi = *(const float4*)(Abase + (size_t)row_a * K + half_a * 4 + 8);
        Asp[row_a * 4 + ((2 * half_a    ) ^ aswz)] =
            make_uint2(pkh(alo.x, alo.y), pkh(ahi.x, ahi.y));
        Asp[row_a * 4 + ((2 * half_a + 1) ^ aswz)] =
            make_uint2(pkh(alo.z, alo.w), pkh(ahi.z, ahi.w));
        float bb[8];
        #pragma unroll
        for (int i = 0; i < 4; i++) {
            bb[i]     = Bbase[(size_t)(kh_b + i) * N + n_b];
            bb[4 + i] = Bbase[(size_t)(kh_b + 8 + i) * N + n_b];
        }
        const int cb0 = kh_b >> 1;        // 0 or 2
        Bsp[(cb0    ) * 132 + n_b] = make_uint2(pkh(bb[0], bb[1]), pkh(bb[4], bb[5]));
        Bsp[(cb0 + 1) * 132 + n_b] = make_uint2(pkh(bb[2], bb[3]), pkh(bb[6], bb[7]));
    }
    __syncthreads();

    for (int t = 0; t < NT; t++) {
        float4 palo, pahi;
        float pb[8];
        if (t + 1 < NT) {
            const int k0 = (t + 1) * BK;
            palo = *(const float4*)(Abase + (size_t)row_a * K + k0 + half_a * 4);
            pahi = *(const float4*)(Abase + (size_t)row_a * K + k0 + half_a * 4 + 8);
            #pragma unroll
            for (int i = 0; i < 4; i++) {
                pb[i]     = Bbase[(size_t)(k0 + kh_b + i) * N + n_b];
                pb[4 + i] = Bbase[(size_t)(k0 + kh_b + 8 + i) * N + n_b];
            }
        }

        // ---- compute: one m16n8k16 step over the whole BK=16 tile ----
        {
            uint32_t af[2][4];
            #pragma unroll
            for (int mt = 0; mt < 2; mt++) {
                const int r0 = wm + mt * 16 + gid;
                const uint2 u0 = Asp[r0 * 4 + crA];
                const uint2 u1 = Asp[(r0 + 8) * 4 + crA];
                af[mt][0] = u0.x; af[mt][1] = u1.x;
                af[mt][2] = u0.y; af[mt][3] = u1.y;
            }
            uint32_t bf[8][2];
            #pragma unroll
            for (int nt = 0; nt < 8; nt++) {
                const uint2 v = Bsp[cB * 132 + wn + nt * 8 + gid];
                bf[nt][0] = v.x; bf[nt][1] = v.y;
            }
            #pragma unroll
            for (int mt = 0; mt < 2; mt++)
                #pragma unroll
                for (int nt = 0; nt < 8; nt++)
                    MMA_F16(acc[mt][nt], af[mt], bf[nt]);
        }
        __syncthreads();

        if (t + 1 < NT) {
            Asp[row_a * 4 + ((2 * half_a    ) ^ aswz)] =
                make_uint2(pkh(palo.x, palo.y), pkh(pahi.x, pahi.y));
            Asp[row_a * 4 + ((2 * half_a + 1) ^ aswz)] =
                make_uint2(pkh(palo.z, palo.w), pkh(pahi.z, pahi.w));
            const int cb0 = kh_b >> 1;
            Bsp[(cb0    ) * 132 + n_b] = make_uint2(pkh(pb[0], pb[1]), pkh(pb[4], pb[5]));
            Bsp[(cb0 + 1) * 132 + n_b] = make_uint2(pkh(pb[2], pb[3]), pkh(pb[6], pb[7]));
            __syncthreads();
        }
    }

    // ---- epilogue (C fragment layout identical to tf32 m16n8) ----
    #pragma unroll
    for (int mt = 0; mt < 2; mt++) {
        const int m0 = cRow * BM + wm + mt * 16 + gid;
        #pragma unroll
        for (int nt = 0; nt < 8; nt++) {
            const int n0 = cCol * BN + wn + nt * 8 + cB * 2;
            epi_store<EPI>(m0,     n0, make_float2(acc[mt][nt][0], acc[mt][nt][1]),
                           N, bias, resid, C, e0, e1, e2);
            epi_store<EPI>(m0 + 8, n0, make_float2(acc[mt][nt][2], acc[mt][nt][3]),
                           N, bias, resid, C, e0, e1, e2);
        }
    }
}

// ---------------------------------------------------------------------------
// Tensor-core flash attention (tf32 mma.sync), unchanged from R4.
// ---------------------------------------------------------------------------
#define KVT 32
#define NTILES (L_ / KVT)

__global__ __launch_bounds__(256, 2)
void attn_mma_k(const float* __restrict__ q, const float* __restrict__ k,
                const float* __restrict__ v, float* __restrict__ out)
{
    __shared__ float Ks[2][KVT][68];
    __shared__ float Vs[2][KVT][72];

    const int bh   = blockIdx.y;
    const int b    = bh >> 4;
    const int h    = bh & 15;
    const int tid  = threadIdx.x;
    const int wid  = tid >> 5;
    const int lane = tid & 31;
    const int gid  = lane >> 2;
    const int tg   = lane & 3;

    const float* kbase = k + (size_t)bh * L_ * HD_;
    const float* vbase = v + (size_t)bh * L_ * HD_;

    const int ld_row0 = tid >> 4;
    const int ld_row1 = ld_row0 + 16;
    const int ld_c    = (tid & 15) * 4;
    const uint32_t sK0 = smem_u32(&Ks[0][0][0]);
    const uint32_t sV0 = smem_u32(&Vs[0][0][0]);

    const int qr = blockIdx.x * 128 + wid * 16 + gid;
    const float* qp = q + (size_t)bh * L_ * HD_;
    const float SC = 0.18033688011112042f;  // log2(e) / 8
    uint32_t qf[8][4];
    #pragma unroll
    for (int kq = 0; kq < 8; kq++) {
        qf[kq][0] = __float_as_uint(qp[(size_t)qr      * HD_ + 8 * kq + tg    ] * SC);
        qf[kq][1] = __float_as_uint(qp[(size_t)(qr + 8) * HD_ + 8 * kq + tg    ] * SC);
        qf[kq][2] = __float_as_uint(qp[(size_t)qr      * HD_ + 8 * kq + tg + 4] * SC);
        qf[kq][3] = __float_as_uint(qp[(size_t)(qr + 8) * HD_ + 8 * kq + tg + 4] * SC);
    }

    float oacc[8][4];
    #pragma unroll
    for (int on = 0; on < 8; on++)
        #pragma unroll
        for (int i = 0; i < 4; i++) oacc[on][i] = 0.f;
    float mr0 = -1e30f, mr1 = -1e30f, ls0 = 0.f, ls1 = 0.f;

    {
        cpa16(sK0 + (ld_row0 * 68 + ld_c) * 4, kbase + (size_t)ld_row0 * HD_ + ld_c);
        cpa16(sK0 + (ld_row1 * 68 + ld_c) * 4, kbase + (size_t)ld_row1 * HD_ + ld_c);
        cpa16(sV0 + (ld_row0 * 72 + ld_c) * 4, vbase + (size_t)ld_row0 * HD_ + ld_c);
        cpa16(sV0 + (ld_row1 * 72 + ld_c) * 4, vbase + (size_t)ld_row1 * HD_ + ld_c);
        asm volatile("cp.async.commit_group;");
    }

    for (int t = 0; t < NTILES; t++) {
        const int cur = t & 1;
        if (t + 1 < NTILES) {
            const int nb = (t + 1) & 1;
            const float* ksrc = kbase + (size_t)(t + 1) * KVT * HD_;
            const float* vsrc = vbase + (size_t)(t + 1) * KVT * HD_;
            const uint32_t dK = sK0 + nb * (KVT * 68 * 4);
            const uint32_t dV = sV0 + nb * (KVT * 72 * 4);
            cpa16(dK + (ld_row0 * 68 + ld_c) * 4, ksrc + (size_t)ld_row0 * HD_ + ld_c);
            cpa16(dK + (ld_row1 * 68 + ld_c) * 4, ksrc + (size_t)ld_row1 * HD_ + ld_c);
            cpa16(dV + (ld_row0 * 72 + ld_c) * 4, vsrc + (size_t)ld_row0 * HD_ + ld_c);
            cpa16(dV + (ld_row1 * 72 + ld_c) * 4, vsrc + (size_t)ld_row1 * HD_ + ld_c);
            asm volatile("cp.async.commit_group;");
            asm volatile("cp.async.wait_group 1;");
        } else {
            asm volatile("cp.async.wait_group 0;");
        }
        __syncthreads();

        float sacc[4][4];
        #pragma unroll
        for (int nt = 0; nt < 4; nt++)
            #pragma unroll
            for (int i = 0; i < 4; i++) sacc[nt][i] = 0.f;

        #pragma unroll
        for (int kq = 0; kq < 8; kq++) {
            uint32_t bf[4][2];
            #pragma unroll
            for (int nt = 0; nt < 4; nt++) {
                bf[nt][0] = *(const uint32_t*)&Ks[cur][nt * 8 + gid][8 * kq + tg    ];
                bf[nt][1] = *(const uint32_t*)&Ks[cur][nt * 8 + gid][8 * kq + tg + 4];
            }
            #pragma unroll
            for (int nt = 0; nt < 4; nt++)
                MMA_TF32(sacc[nt], qf[kq], bf[nt]);
        }

        float m0 = mr0, m1 = mr1;
        #pragma unroll
        for (int nt = 0; nt < 4; nt++) {
            m0 = fmaxf(m0, fmaxf(sacc[nt][0], sacc[nt][1]));
            m1 = fmaxf(m1, fmaxf(sacc[nt][2], sacc[nt][3]));
        }
        m0 = fmaxf(m0, __shfl_xor_sync(0xffffffffu, m0, 1));
        m0 = fmaxf(m0, __shfl_xor_sync(0xffffffffu, m0, 2));
        m1 = fmaxf(m1, __shfl_xor_sync(0xffffffffu, m1, 1));
        m1 = fmaxf(m1, __shfl_xor_sync(0xffffffffu, m1, 2));

        const float sc0 = ex2f(mr0 - m0);
        const float sc1 = ex2f(mr1 - m1);
        mr0 = m0; mr1 = m1;

        float rs0 = 0.f, rs1 = 0.f;
        #pragma unroll
        for (int nt = 0; nt < 4; nt++) {
            sacc[nt][0] = ex2f(sacc[nt][0] - m0);
            sacc[nt][1] = ex2f(sacc[nt][1] - m0);
            sacc[nt][2] = ex2f(sacc[nt][2] - m1);
            sacc[nt][3] = ex2f(sacc[nt][3] - m1);
            rs0 += sacc[nt][0] + sacc[nt][1];
            rs1 += sacc[nt][2] + sacc[nt][3];
        }
        rs0 += __shfl_xor_sync(0xffffffffu, rs0, 1);
        rs0 += __shfl_xor_sync(0xffffffffu, rs0, 2);
        rs1 += __shfl_xor_sync(0xffffffffu, rs1, 1);
        rs1 += __shfl_xor_sync(0xffffffffu, rs1, 2);
        ls0 = ls0 * sc0 + rs0;
        ls1 = ls1 * sc1 + rs1;

        #pragma unroll
        for (int on = 0; on < 8; on++) {
            oacc[on][0] *= sc0;
            oacc[on][1] *= sc0;
            oacc[on][2] *= sc1;
            oacc[on][3] *= sc1;
        }

        const int base = lane & ~3;
        const int src0 = base + (tg >> 1);
        const int src2 = src0 + 2;
        #pragma unroll
        for (int kb = 0; kb < 4; kb++) {
            uint32_t af[4];
            {
                float x, y;
                x = __shfl_sync(0xffffffffu, sacc[kb][0], src0);
                y = __shfl_sync(0xffffffffu, sacc[kb][1], src0);
                af[0] = __float_as_uint((tg & 1) ? y : x);
                x = __shfl_sync(0xffffffffu, sacc[kb][2], src0);
                y = __shfl_sync(0xffffffffu, sacc[kb][3], src0);
                af[1] = __float_as_uint((tg & 1) ? y : x);
                x = __shfl_sync(0xffffffffu, sacc[kb][0], src2);
                y = __shfl_sync(0xffffffffu, sacc[kb][1], src2);
                af[2] = __float_as_uint((tg & 1) ? y : x);
                x = __shfl_sync(0xffffffffu, sacc[kb][2], src2);
                y = __shfl_sync(0xffffffffu, sacc[kb][3], src2);
                af[3] = __float_as_uint((tg & 1) ? y : x);
            }
            #pragma unroll
            for (int on = 0; on < 8; on++) {
                uint32_t bv[2];
                bv[0] = *(const uint32_t*)&Vs[cur][kb * 8 + tg    ][on * 8 + gid];
                bv[1] = *(const uint32_t*)&Vs[cur][kb * 8 + tg + 4][on * 8 + gid];
                MMA_TF32(oacc[on], af, bv);
            }
        }
        __syncthreads();
    }

    const float inv0 = 1.f / ls0;
    const float inv1 = 1.f / ls1;
    float* op0 = out + ((size_t)qr       * B_ + b) * D_ + h * HD_;
    float* op1 = out + ((size_t)(qr + 8) * B_ + b) * D_ + h * HD_;
    #pragma unroll
    for (int on = 0; on < 8; on++) {
        const int c0 = on * 8 + tg * 2;
        *(float2*)(op0 + c0) = make_float2(oacc[on][0] * inv0, oacc[on][1] * inv0);
        *(float2*)(op1 + c0) = make_float2(oacc[on][2] * inv1, oacc[on][3] * inv1);
    }
}

// ---------------------------------------------------------------------------
// Launch
// ---------------------------------------------------------------------------
extern "C" void kernel_launch(void* const* d_in, const int* in_sizes, int n_in,
                              void* d_out, int out_size)
{
    const float* x      = (const float*)d_in[0];
    const float* ln1_g  = (const float*)d_in[1];
    const float* ln1_b  = (const float*)d_in[2];
    const float* w_attn = (const float*)d_in[3];
    const float* b_attn = (const float*)d_in[4];
    const float* w_proj = (const float*)d_in[5];
    const float* b_proj = (const float*)d_in[6];
    const float* ln2_g  = (const float*)d_in[7];
    const float* ln2_b  = (const float*)d_in[8];
    const float* w_fc   = (const float*)d_in[9];
    const float* b_fc   = (const float*)d_in[10];
    const float* w_out  = (const float*)d_in[11];
    const float* b_out  = (const float*)d_in[12];

    float* out  = (float*)d_out;
    float* kout = out  + (size_t)L_ * B_ * D_;                 // present[0]
    float* vout = kout + (size_t)B_ * H_ * L_ * HD_;           // present[1]

    float *hptr, *qptr, *atptr, *x1ptr, *mptr;
    cudaGetSymbolAddress((void**)&hptr,  g_h);
    cudaGetSymbolAddress((void**)&qptr,  g_q);
    cudaGetSymbolAddress((void**)&atptr, g_at);
    cudaGetSymbolAddress((void**)&x1ptr, g_x1);
    cudaGetSymbolAddress((void**)&mptr,  g_m);

    // 1) LN1
    ln_k<<<MTOK, 256>>>(x, ln1_g, ln1_b, hptr);

    // 2) QKV GEMM [4096,1024]@[1024,3072]; scatter q->scratch, k/v->present
    hgemm_k<0><<<dim3(3 * D_ / 128, MTOK / 128), 256>>>(
        hptr, w_attn, b_attn, nullptr, nullptr, MTOK, 3 * D_, D_,
        qptr, kout, vout);

    // 3) tensor-core attention -> token-major a
    attn_mma_k<<<dim3(L_ / 128, B_ * H_), 256>>>(qptr, kout, vout, atptr);

    // 4) proj + residual -> x1
    hgemm_k<1><<<dim3(D_ / 128, MTOK / 128), 256>>>(
        atptr, w_proj, b_proj, x, x1ptr, MTOK, D_, D_,
        nullptr, nullptr, nullptr);

    // 5) LN2
    ln_k<<<MTOK, 256>>>(x1ptr, ln2_g, ln2_b, hptr);

    // 6) FC + GELU
    hgemm_k<2><<<dim3(DFF_ / 128, MTOK / 128), 256>>>(
        hptr, w_fc, b_fc, nullptr, mptr, MTOK, DFF_, D_,
        nullptr, nullptr, nullptr);

    // 7) out proj + residual -> final x
    hgemm_k<1><<<dim3(D_ / 128, MTOK / 128), 256>>>(
        mptr, w_out, b_out, x1ptr, out, MTOK, D_, DFF_,
        nullptr, nullptr, nullptr);
}

// round 6
// speedup vs baseline: 5.6824x; 1.3091x over previous
#include <cuda_runtime.h>
#include <cuda_fp16.h>
#include <math.h>
#include <stdint.h>

// Problem dims (fixed)
#define L_    2048
#define B_    2
#define D_    1024
#define H_    16
#define HD_   64
#define DFF_  4096
#define MTOK  4096   // L*B tokens

// ---------------------------------------------------------------------------
// Scratch (static device globals)
// ---------------------------------------------------------------------------
__device__ __half g_h16 [(size_t)MTOK * D_];    // LN output (fp16, GEMM A)
__device__ __half g_at16[(size_t)MTOK * D_];    // attention out (fp16, proj A)
__device__ __half g_m16 [(size_t)MTOK * DFF_];  // gelu(fc) (fp16, out-GEMM A)
__device__ __half g_w16 [12u * 1024 * 1024];    // fp16 weights (wa|wp|wf|wo)
__device__ float  g_q  [(size_t)B_ * H_ * L_ * HD_];
__device__ float  g_x1 [(size_t)MTOK * D_];     // x + attn (residual 1)

#define WA_OFF 0
#define WP_OFF (3u * 1024 * 1024)
#define WF_OFF (4u * 1024 * 1024)
#define WO_OFF (8u * 1024 * 1024)

// ---------------------------------------------------------------------------
// helpers (baseline PTX only — no tcgen05 on this compute_103 build)
// ---------------------------------------------------------------------------
__device__ __forceinline__ float ex2f(float x) {
    float y;
    asm("ex2.approx.f32 %0, %1;" : "=f"(y) : "f"(x));
    return y;
}
__device__ __forceinline__ uint32_t smem_u32(const void* p) {
    uint32_t a;
    asm("{ .reg .u64 t; cvta.to.shared.u64 t, %1; cvt.u32.u64 %0, t; }"
        : "=r"(a) : "l"(p));
    return a;
}
__device__ __forceinline__ void cpa16(uint32_t dst, const void* src) {
    asm volatile("cp.async.cg.shared.global [%0], [%1], 16;"
                 :: "r"(dst), "l"(src));
}

#define LDSM4(r0, r1, r2, r3, addr)                                         \
    asm volatile("ldmatrix.sync.aligned.m8n8.x4.shared.b16 "                \
                 "{%0,%1,%2,%3}, [%4];"                                     \
                 : "=r"(r0), "=r"(r1), "=r"(r2), "=r"(r3) : "r"(addr))

#define LDSM4T(r0, r1, r2, r3, addr)                                        \
    asm volatile("ldmatrix.sync.aligned.m8n8.x4.trans.shared.b16 "          \
                 "{%0,%1,%2,%3}, [%4];"                                     \
                 : "=r"(r0), "=r"(r1), "=r"(r2), "=r"(r3) : "r"(addr))

#define MMA_F16(d, a, b)                                                    \
    asm volatile(                                                           \
        "mma.sync.aligned.m16n8k16.row.col.f32.f16.f16.f32 "                \
        "{%0,%1,%2,%3}, {%4,%5,%6,%7}, {%8,%9}, {%0,%1,%2,%3};"             \
        : "+f"((d)[0]), "+f"((d)[1]), "+f"((d)[2]), "+f"((d)[3])            \
        : "r"((a)[0]), "r"((a)[1]), "r"((a)[2]), "r"((a)[3]),               \
          "r"((b)[0]), "r"((b)[1]))

#define MMA_TF32(d, a, b)                                                   \
    asm volatile(                                                           \
        "mma.sync.aligned.m16n8k8.row.col.f32.tf32.tf32.f32 "               \
        "{%0,%1,%2,%3}, {%4,%5,%6,%7}, {%8,%9}, {%0,%1,%2,%3};"             \
        : "+f"((d)[0]), "+f"((d)[1]), "+f"((d)[2]), "+f"((d)[3])            \
        : "r"((a)[0]), "r"((a)[1]), "r"((a)[2]), "r"((a)[3]),               \
          "r"((b)[0]), "r"((b)[1]))

// ---------------------------------------------------------------------------
// f32 -> f16 conversion (weights pre-pass)
// ---------------------------------------------------------------------------
__global__ __launch_bounds__(256)
void cvt_k(const float* __restrict__ s, __half* __restrict__ d)
{
    const int i = blockIdx.x * 256 + threadIdx.x;
    const float4 v = ((const float4*)s)[i];
    __half2* dp = (__half2*)d + 2 * (size_t)i;
    dp[0] = __floats2half2_rn(v.x, v.y);
    dp[1] = __floats2half2_rn(v.z, v.w);
}

// ---------------------------------------------------------------------------
// LayerNorm: one block per token row (1024 elems); writes fp16
// ---------------------------------------------------------------------------
__global__ __launch_bounds__(256)
void ln_k(const float* __restrict__ x, const float* __restrict__ g,
          const float* __restrict__ b, __half* __restrict__ out)
{
    const int row = blockIdx.x;
    const int tid = threadIdx.x;
    const float4 v = *(const float4*)(x + (size_t)row * D_ + tid * 4);

    float s = v.x + v.y + v.z + v.w;
    float q = v.x * v.x + v.y * v.y + v.z * v.z + v.w * v.w;
    #pragma unroll
    for (int o = 16; o > 0; o >>= 1) {
        s += __shfl_down_sync(0xffffffffu, s, o);
        q += __shfl_down_sync(0xffffffffu, q, o);
    }
    __shared__ float ss[8], sq[8];
    const int w = tid >> 5, ln = tid & 31;
    if (ln == 0) { ss[w] = s; sq[w] = q; }
    __syncthreads();
    float S = 0.f, Q = 0.f;
    #pragma unroll
    for (int i = 0; i < 8; i++) { S += ss[i]; Q += sq[i]; }

    const float mu  = S * (1.f / D_);
    const float var = Q * (1.f / D_) - mu * mu;
    const float rs  = rsqrtf(var + 1e-5f);

    const float4 gv = *(const float4*)(g + tid * 4);
    const float4 bv = *(const float4*)(b + tid * 4);
    __half2 h0 = __floats2half2_rn((v.x - mu) * rs * gv.x + bv.x,
                                   (v.y - mu) * rs * gv.y + bv.y);
    __half2 h1 = __floats2half2_rn((v.z - mu) * rs * gv.z + bv.z,
                                   (v.w - mu) * rs * gv.w + bv.w);
    __half2* op = (__half2*)(out + (size_t)row * D_) + tid * 2;
    op[0] = h0;
    op[1] = h1;
}

// ---------------------------------------------------------------------------
// Epilogue helper: consume one float2 at (m, n), n even.
//   EPI 0: scatter QKV -> q scratch (f32) / k,v (present region, f32)
//   EPI 1: C = acc + bias + resid (f32)
//   EPI 2: Ch = gelu(acc + bias) (f16)
// ---------------------------------------------------------------------------
template <int EPI>
__device__ __forceinline__ void epi_store(
    int m, int n, float2 v, int N,
    const float* __restrict__ bias, const float* __restrict__ resid,
    float* __restrict__ C, __half* __restrict__ Ch,
    float* __restrict__ e0, float* __restrict__ e1, float* __restrict__ e2)
{
    const float2 bv = *(const float2*)(bias + n);
    v.x += bv.x;
    v.y += bv.y;
    if (EPI == 0) {
        const int part = n >> 10;
        const int d    = n & 1023;
        const int hh   = d >> 6;
        const int hd   = d & 63;
        const int l    = m >> 1;     // token m = l*B + b, B=2
        const int bb   = m & 1;
        const size_t idx = (((size_t)(bb * H_ + hh) * L_) + l) * HD_ + hd;
        float* dst = (part == 0) ? e0 : (part == 1) ? e1 : e2;
        *(float2*)(dst + idx) = v;
    } else if (EPI == 1) {
        const size_t idx = (size_t)m * N + n;
        const float2 rv = *(const float2*)(resid + idx);
        v.x += rv.x;
        v.y += rv.y;
        *(float2*)(C + idx) = v;
    } else {
        const float t0 = tanhf(0.7978845608028654f *
                               (v.x + 0.044715f * v.x * v.x * v.x));
        const float t1 = tanhf(0.7978845608028654f *
                               (v.y + 0.044715f * v.y * v.y * v.y));
        *(__half2*)(Ch + (size_t)m * N + n) =
            __floats2half2_rn(0.5f * v.x * (1.f + t0), 0.5f * v.y * (1.f + t1));
    }
}

// ---------------------------------------------------------------------------
// fp16 GEMM, cp.async double-buffered: C = A[M,K] @ B[K,N] (+bias, epilogue).
// A, B fp16 in global. CTA 128x128, BK=32, 256 threads (8 warps 4x2).
// Smem: As [128][40] halfs (80B row stride -> ldmatrix conflict-free),
//       Bs [32][136] halfs (272B stride -> trans ldmatrix conflict-free).
// ---------------------------------------------------------------------------
template <int EPI>
__global__ __launch_bounds__(256, 2)
void hgemm_k(const __half* __restrict__ A, const __half* __restrict__ Bm,
             const float* __restrict__ bias, const float* __restrict__ resid,
             float* __restrict__ C, __half* __restrict__ Ch, int M, int N, int K,
             float* __restrict__ e0, float* __restrict__ e1, float* __restrict__ e2)
{
    constexpr int BM = 128, BN = 128, BK = 32;
    __shared__ __half As[2][BM * 40];
    __shared__ __half Bs[2][BK * 136];

    const int tid  = threadIdx.x;
    const int wid  = tid >> 5;
    const int lane = tid & 31;
    const int wm   = (wid & 3) * 32;
    const int wn   = (wid >> 2) * 64;
    const int gid  = lane >> 2;
    const int tg   = lane & 3;
    const int cCol = blockIdx.x, cRow = blockIdx.y;

    const __half* Abase = A  + (size_t)cRow * BM * K;
    const __half* Bbase = Bm + (size_t)cCol * BN;

    // cp.async writer coords
    const int arow = tid >> 1;                 // 0..127
    const int ac0  = (tid & 1) * 2;            // chunk 0/2 (8 halfs each)
    const int brow = tid >> 4;                 // 0..15 (+16)
    const int bc   = tid & 15;                 // 16 chunks per B row
    const uint32_t sA0 = smem_u32(&As[0][0]);
    const uint32_t sB0 = smem_u32(&Bs[0][0]);

    // ldmatrix reader base offsets (lane-dependent)
    const int a_r  = lane & 15;                // row within m16
    const int a_c  = (lane >> 4) * 8;          // k-half select
    const int b_k  = lane & 15;                // k row within k16
    const int b_n  = (lane >> 4) * 8;          // n-half select

    float acc[2][8][4];
    #pragma unroll
    for (int mt = 0; mt < 2; mt++)
        #pragma unroll
        for (int nt = 0; nt < 8; nt++)
            #pragma unroll
            for (int i = 0; i < 4; i++) acc[mt][nt][i] = 0.f;

    const int NT = K / BK;

    // prologue: stages 0 and 1
    #pragma unroll
    for (int p = 0; p < 2; p++) {
        const int k0 = p * BK;
        const uint32_t dA = sA0 + p * (BM * 40 * 2);
        const uint32_t dB = sB0 + p * (BK * 136 * 2);
        cpa16(dA + (arow * 40 + (ac0    ) * 8) * 2, Abase + (size_t)arow * K + k0 + (ac0    ) * 8);
        cpa16(dA + (arow * 40 + (ac0 + 1) * 8) * 2, Abase + (size_t)arow * K + k0 + (ac0 + 1) * 8);
        cpa16(dB + ((brow     ) * 136 + bc * 8) * 2, Bbase + (size_t)(k0 + brow     ) * N + bc * 8);
        cpa16(dB + ((brow + 16) * 136 + bc * 8) * 2, Bbase + (size_t)(k0 + brow + 16) * N + bc * 8);
        asm volatile("cp.async.commit_group;");
    }

    for (int t = 0; t < NT; t++) {
        if (t < NT - 1) asm volatile("cp.async.wait_group 1;");
        else            asm volatile("cp.async.wait_group 0;");
        __syncthreads();

        const int s = t & 1;
        const uint32_t aS = sA0 + s * (BM * 40 * 2);
        const uint32_t bS = sB0 + s * (BK * 136 * 2);

        #pragma unroll
        for (int ks = 0; ks < 2; ks++) {
            uint32_t af[2][4];
            #pragma unroll
            for (int mt = 0; mt < 2; mt++) {
                const uint32_t addr =
                    aS + ((wm + mt * 16 + a_r) * 40 + ks * 16 + a_c) * 2;
                LDSM4(af[mt][0], af[mt][1], af[mt][2], af[mt][3], addr);
            }
            uint32_t bf[8][2];
            #pragma unroll
            for (int ng = 0; ng < 4; ng++) {
                const uint32_t addr =
                    bS + ((ks * 16 + b_k) * 136 + wn + ng * 16 + b_n) * 2;
                LDSM4T(bf[2 * ng][0], bf[2 * ng][1],
                       bf[2 * ng + 1][0], bf[2 * ng + 1][1], addr);
            }
            #pragma unroll
            for (int mt = 0; mt < 2; mt++)
                #pragma unroll
                for (int nt = 0; nt < 8; nt++)
                    MMA_F16(acc[mt][nt], af[mt], bf[nt]);
        }
        __syncthreads();

        if (t + 2 < NT) {
            const int k0 = (t + 2) * BK;
            const uint32_t dA = sA0 + s * (BM * 40 * 2);
            const uint32_t dB = sB0 + s * (BK * 136 * 2);
            cpa16(dA + (arow * 40 + (ac0    ) * 8) * 2, Abase + (size_t)arow * K + k0 + (ac0    ) * 8);
            cpa16(dA + (arow * 40 + (ac0 + 1) * 8) * 2, Abase + (size_t)arow * K + k0 + (ac0 + 1) * 8);
            cpa16(dB + ((brow     ) * 136 + bc * 8) * 2, Bbase + (size_t)(k0 + brow     ) * N + bc * 8);
            cpa16(dB + ((brow + 16) * 136 + bc * 8) * 2, Bbase + (size_t)(k0 + brow + 16) * N + bc * 8);
            asm volatile("cp.async.commit_group;");
        }
    }

    // epilogue (m16n8 C-fragment layout)
    #pragma unroll
    for (int mt = 0; mt < 2; mt++) {
        const int m0 = cRow * BM + wm + mt * 16 + gid;
        #pragma unroll
        for (int nt = 0; nt < 8; nt++) {
            const int n0 = cCol * BN + wn + nt * 8 + tg * 2;
            epi_store<EPI>(m0,     n0, make_float2(acc[mt][nt][0], acc[mt][nt][1]),
                           N, bias, resid, C, Ch, e0, e1, e2);
            epi_store<EPI>(m0 + 8, n0, make_float2(acc[mt][nt][2], acc[mt][nt][3]),
                           N, bias, resid, C, Ch, e0, e1, e2);
        }
    }
}

// ---------------------------------------------------------------------------
// Tensor-core flash attention (tf32 mma.sync); output stored fp16 for proj.
// ---------------------------------------------------------------------------
#define KVT 32
#define NTILES (L_ / KVT)

__global__ __launch_bounds__(256, 2)
void attn_mma_k(const float* __restrict__ q, const float* __restrict__ k,
                const float* __restrict__ v, __half* __restrict__ out)
{
    __shared__ float Ks[2][KVT][68];
    __shared__ float Vs[2][KVT][72];

    const int bh   = blockIdx.y;
    const int b    = bh >> 4;
    const int h    = bh & 15;
    const int tid  = threadIdx.x;
    const int wid  = tid >> 5;
    const int lane = tid & 31;
    const int gid  = lane >> 2;
    const int tg   = lane & 3;

    const float* kbase = k + (size_t)bh * L_ * HD_;
    const float* vbase = v + (size_t)bh * L_ * HD_;

    const int ld_row0 = tid >> 4;
    const int ld_row1 = ld_row0 + 16;
    const int ld_c    = (tid & 15) * 4;
    const uint32_t sK0 = smem_u32(&Ks[0][0][0]);
    const uint32_t sV0 = smem_u32(&Vs[0][0][0]);

    const int qr = blockIdx.x * 128 + wid * 16 + gid;
    const float* qp = q + (size_t)bh * L_ * HD_;
    const float SC = 0.18033688011112042f;  // log2(e) / 8
    uint32_t qf[8][4];
    #pragma unroll
    for (int kq = 0; kq < 8; kq++) {
        qf[kq][0] = __float_as_uint(qp[(size_t)qr      * HD_ + 8 * kq + tg    ] * SC);
        qf[kq][1] = __float_as_uint(qp[(size_t)(qr + 8) * HD_ + 8 * kq + tg    ] * SC);
        qf[kq][2] = __float_as_uint(qp[(size_t)qr      * HD_ + 8 * kq + tg + 4] * SC);
        qf[kq][3] = __float_as_uint(qp[(size_t)(qr + 8) * HD_ + 8 * kq + tg + 4] * SC);
    }

    float oacc[8][4];
    #pragma unroll
    for (int on = 0; on < 8; on++)
        #pragma unroll
        for (int i = 0; i < 4; i++) oacc[on][i] = 0.f;
    float mr0 = -1e30f, mr1 = -1e30f, ls0 = 0.f, ls1 = 0.f;

    {
        cpa16(sK0 + (ld_row0 * 68 + ld_c) * 4, kbase + (size_t)ld_row0 * HD_ + ld_c);
        cpa16(sK0 + (ld_row1 * 68 + ld_c) * 4, kbase + (size_t)ld_row1 * HD_ + ld_c);
        cpa16(sV0 + (ld_row0 * 72 + ld_c) * 4, vbase + (size_t)ld_row0 * HD_ + ld_c);
        cpa16(sV0 + (ld_row1 * 72 + ld_c) * 4, vbase + (size_t)ld_row1 * HD_ + ld_c);
        asm volatile("cp.async.commit_group;");
    }

    for (int t = 0; t < NTILES; t++) {
        const int cur = t & 1;
        if (t + 1 < NTILES) {
            const int nb = (t + 1) & 1;
            const float* ksrc = kbase + (size_t)(t + 1) * KVT * HD_;
            const float* vsrc = vbase + (size_t)(t + 1) * KVT * HD_;
            const uint32_t dK = sK0 + nb * (KVT * 68 * 4);
            const uint32_t dV = sV0 + nb * (KVT * 72 * 4);
            cpa16(dK + (ld_row0 * 68 + ld_c) * 4, ksrc + (size_t)ld_row0 * HD_ + ld_c);
            cpa16(dK + (ld_row1 * 68 + ld_c) * 4, ksrc + (size_t)ld_row1 * HD_ + ld_c);
            cpa16(dV + (ld_row0 * 72 + ld_c) * 4, vsrc + (size_t)ld_row0 * HD_ + ld_c);
            cpa16(dV + (ld_row1 * 72 + ld_c) * 4, vsrc + (size_t)ld_row1 * HD_ + ld_c);
            asm volatile("cp.async.commit_group;");
            asm volatile("cp.async.wait_group 1;");
        } else {
            asm volatile("cp.async.wait_group 0;");
        }
        __syncthreads();

        float sacc[4][4];
        #pragma unroll
        for (int nt = 0; nt < 4; nt++)
            #pragma unroll
            for (int i = 0; i < 4; i++) sacc[nt][i] = 0.f;

        #pragma unroll
        for (int kq = 0; kq < 8; kq++) {
            uint32_t bf[4][2];
            #pragma unroll
            for (int nt = 0; nt < 4; nt++) {
                bf[nt][0] = *(const uint32_t*)&Ks[cur][nt * 8 + gid][8 * kq + tg    ];
                bf[nt][1] = *(const uint32_t*)&Ks[cur][nt * 8 + gid][8 * kq + tg + 4];
            }
            #pragma unroll
            for (int nt = 0; nt < 4; nt++)
                MMA_TF32(sacc[nt], qf[kq], bf[nt]);
        }

        float m0 = mr0, m1 = mr1;
        #pragma unroll
        for (int nt = 0; nt < 4; nt++) {
            m0 = fmaxf(m0, fmaxf(sacc[nt][0], sacc[nt][1]));
            m1 = fmaxf(m1, fmaxf(sacc[nt][2], sacc[nt][3]));
        }
        m0 = fmaxf(m0, __shfl_xor_sync(0xffffffffu, m0, 1));
        m0 = fmaxf(m0, __shfl_xor_sync(0xffffffffu, m0, 2));
        m1 = fmaxf(m1, __shfl_xor_sync(0xffffffffu, m1, 1));
        m1 = fmaxf(m1, __shfl_xor_sync(0xffffffffu, m1, 2));

        const float sc0 = ex2f(mr0 - m0);
        const float sc1 = ex2f(mr1 - m1);
        mr0 = m0; mr1 = m1;

        float rs0 = 0.f, rs1 = 0.f;
        #pragma unroll
        for (int nt = 0; nt < 4; nt++) {
            sacc[nt][0] = ex2f(sacc[nt][0] - m0);
            sacc[nt][1] = ex2f(sacc[nt][1] - m0);
            sacc[nt][2] = ex2f(sacc[nt][2] - m1);
            sacc[nt][3] = ex2f(sacc[nt][3] - m1);
            rs0 += sacc[nt][0] + sacc[nt][1];
            rs1 += sacc[nt][2] + sacc[nt][3];
        }
        rs0 += __shfl_xor_sync(0xffffffffu, rs0, 1);
        rs0 += __shfl_xor_sync(0xffffffffu, rs0, 2);
        rs1 += __shfl_xor_sync(0xffffffffu, rs1, 1);
        rs1 += __shfl_xor_sync(0xffffffffu, rs1, 2);
        ls0 = ls0 * sc0 + rs0;
        ls1 = ls1 * sc1 + rs1;

        #pragma unroll
        for (int on = 0; on < 8; on++) {
            oacc[on][0] *= sc0;
            oacc[on][1] *= sc0;
            oacc[on][2] *= sc1;
            oacc[on][3] *= sc1;
        }

        const int base = lane & ~3;
        const int src0 = base + (tg >> 1);
        const int src2 = src0 + 2;
        #pragma unroll
        for (int kb = 0; kb < 4; kb++) {
            uint32_t af[4];
            {
                float x, y;
                x = __shfl_sync(0xffffffffu, sacc[kb][0], src0);
                y = __shfl_sync(0xffffffffu, sacc[kb][1], src0);
                af[0] = __float_as_uint((tg & 1) ? y : x);
                x = __shfl_sync(0xffffffffu, sacc[kb][2], src0);
                y = __shfl_sync(0xffffffffu, sacc[kb][3], src0);
                af[1] = __float_as_uint((tg & 1) ? y : x);
                x = __shfl_sync(0xffffffffu, sacc[kb][0], src2);
                y = __shfl_sync(0xffffffffu, sacc[kb][1], src2);
                af[2] = __float_as_uint((tg & 1) ? y : x);
                x = __shfl_sync(0xffffffffu, sacc[kb][2], src2);
                y = __shfl_sync(0xffffffffu, sacc[kb][3], src2);
                af[3] = __float_as_uint((tg & 1) ? y : x);
            }
            #pragma unroll
            for (int on = 0; on < 8; on++) {
                uint32_t bv[2];
                bv[0] = *(const uint32_t*)&Vs[cur][kb * 8 + tg    ][on * 8 + gid];
                bv[1] = *(const uint32_t*)&Vs[cur][kb * 8 + tg + 4][on * 8 + gid];
                MMA_TF32(oacc[on], af, bv);
            }
        }
        __syncthreads();
    }

    const float inv0 = 1.f / ls0;
    const float inv1 = 1.f / ls1;
    __half* op0 = out + ((size_t)qr       * B_ + b) * D_ + h * HD_;
    __half* op1 = out + ((size_t)(qr + 8) * B_ + b) * D_ + h * HD_;
    #pragma unroll
    for (int on = 0; on < 8; on++) {
        const int c0 = on * 8 + tg * 2;
        *(__half2*)(op0 + c0) =
            __floats2half2_rn(oacc[on][0] * inv0, oacc[on][1] * inv0);
        *(__half2*)(op1 + c0) =
            __floats2half2_rn(oacc[on][2] * inv1, oacc[on][3] * inv1);
    }
}

// ---------------------------------------------------------------------------
// Launch
// ---------------------------------------------------------------------------
extern "C" void kernel_launch(void* const* d_in, const int* in_sizes, int n_in,
                              void* d_out, int out_size)
{
    const float* x      = (const float*)d_in[0];
    const float* ln1_g  = (const float*)d_in[1];
    const float* ln1_b  = (const float*)d_in[2];
    const float* w_attn = (const float*)d_in[3];
    const float* b_attn = (const float*)d_in[4];
    const float* w_proj = (const float*)d_in[5];
    const float* b_proj = (const float*)d_in[6];
    const float* ln2_g  = (const float*)d_in[7];
    const float* ln2_b  = (const float*)d_in[8];
    const float* w_fc   = (const float*)d_in[9];
    const float* b_fc   = (const float*)d_in[10];
    const float* w_out  = (const float*)d_in[11];
    const float* b_out  = (const float*)d_in[12];

    float* out  = (float*)d_out;
    float* kout = out  + (size_t)L_ * B_ * D_;                 // present[0]
    float* vout = kout + (size_t)B_ * H_ * L_ * HD_;           // present[1]

    __half *h16, *at16, *m16, *w16;
    float *qptr, *x1ptr;
    cudaGetSymbolAddress((void**)&h16,  g_h16);
    cudaGetSymbolAddress((void**)&at16, g_at16);
    cudaGetSymbolAddress((void**)&m16,  g_m16);
    cudaGetSymbolAddress((void**)&w16,  g_w16);
    cudaGetSymbolAddress((void**)&qptr, g_q);
    cudaGetSymbolAddress((void**)&x1ptr, g_x1);

    // 0) weights -> fp16 (graph-replayed each call; ~12us)
    cvt_k<<<3 * 1024 * 1024 / 1024, 256>>>(w_attn, w16 + WA_OFF);
    cvt_k<<<1024 * 1024 / 1024,     256>>>(w_proj, w16 + WP_OFF);
    cvt_k<<<4 * 1024 * 1024 / 1024, 256>>>(w_fc,   w16 + WF_OFF);
    cvt_k<<<4 * 1024 * 1024 / 1024, 256>>>(w_out,  w16 + WO_OFF);

    // 1) LN1 -> fp16
    ln_k<<<MTOK, 256>>>(x, ln1_g, ln1_b, h16);

    // 2) QKV GEMM; scatter q->scratch(f32), k/v->present(f32)
    hgemm_k<0><<<dim3(3 * D_ / 128, MTOK / 128), 256>>>(
        h16, w16 + WA_OFF, b_attn, nullptr, nullptr, nullptr, MTOK, 3 * D_, D_,
        qptr, kout, vout);

    // 3) attention -> fp16 token-major
    attn_mma_k<<<dim3(L_ / 128, B_ * H_), 256>>>(qptr, kout, vout, at16);

    // 4) proj + residual -> x1 (f32)
    hgemm_k<1><<<dim3(D_ / 128, MTOK / 128), 256>>>(
        at16, w16 + WP_OFF, b_proj, x, x1ptr, nullptr, MTOK, D_, D_,
        nullptr, nullptr, nullptr);

    // 5) LN2 -> fp16
    ln_k<<<MTOK, 256>>>(x1ptr, ln2_g, ln2_b, h16);

    // 6) FC + GELU -> fp16
    hgemm_k<2><<<dim3(DFF_ / 128, MTOK / 128), 256>>>(
        h16, w16 + WF_OFF, b_fc, nullptr, nullptr, m16, MTOK, DFF_, D_,
        nullptr, nullptr, nullptr);

    // 7) out proj + residual -> final x (f32)
    hgemm_k<1><<<dim3(D_ / 128, MTOK / 128), 256>>>(
        m16, w16 + WO_OFF, b_out, x1ptr, out, nullptr, MTOK, D_, DFF_,
        nullptr, nullptr, nullptr);
}

// round 8
// speedup vs baseline: 7.3019x; 1.2850x over previous
#include <cuda_runtime.h>
#include <cuda_fp16.h>
#include <math.h>
#include <stdint.h>

// Problem dims (fixed)
#define L_    2048
#define B_    2
#define D_    1024
#define H_    16
#define HD_   64
#define DFF_  4096
#define MTOK  4096   // L*B tokens

// ---------------------------------------------------------------------------
// Scratch (static device globals)
// ---------------------------------------------------------------------------
__device__ __half g_h16 [(size_t)MTOK * D_];    // LN output (fp16, GEMM A)
__device__ __half g_at16[(size_t)MTOK * D_];    // attention out (fp16, proj A)
__device__ __half g_m16 [(size_t)MTOK * DFF_];  // gelu(fc) (fp16, out-GEMM A)
__device__ __half g_w16 [12u * 1024 * 1024];    // fp16 weights (wa|wp|wf|wo)
__device__ __half g_q16 [(size_t)B_ * H_ * L_ * HD_];  // scaled q, fp16
__device__ __half g_k16 [(size_t)B_ * H_ * L_ * HD_];
__device__ __half g_v16 [(size_t)B_ * H_ * L_ * HD_];
__device__ float  g_x1 [(size_t)MTOK * D_];     // x + attn (residual 1)

#define WA_OFF 0
#define WP_OFF (3u * 1024 * 1024)
#define WF_OFF (4u * 1024 * 1024)
#define WO_OFF (8u * 1024 * 1024)

#define SCQ 0.18033688011112042f   // log2(e) / sqrt(64)

// ---------------------------------------------------------------------------
// helpers (baseline PTX only — no tcgen05 on this compute_103 build)
// ---------------------------------------------------------------------------
__device__ __forceinline__ float ex2f(float x) {
    float y;
    asm("ex2.approx.f32 %0, %1;" : "=f"(y) : "f"(x));
    return y;
}
__device__ __forceinline__ uint32_t smem_u32(const void* p) {
    uint32_t a;
    asm("{ .reg .u64 t; cvta.to.shared.u64 t, %1; cvt.u32.u64 %0, t; }"
        : "=r"(a) : "l"(p));
    return a;
}
__device__ __forceinline__ void cpa16(uint32_t dst, const void* src) {
    asm volatile("cp.async.cg.shared.global [%0], [%1], 16;"
                 :: "r"(dst), "l"(src));
}
// pack two f32 -> f16x2 {lo, hi}
__device__ __forceinline__ uint32_t pkh(float lo, float hi) {
    uint32_t r;
    asm("cvt.rn.f16x2.f32 %0, %1, %2;" : "=r"(r) : "f"(hi), "f"(lo));
    return r;
}

#define LDSM4(r0, r1, r2, r3, addr)                                         \
    asm volatile("ldmatrix.sync.aligned.m8n8.x4.shared.b16 "                \
                 "{%0,%1,%2,%3}, [%4];"                                     \
                 : "=r"(r0), "=r"(r1), "=r"(r2), "=r"(r3) : "r"(addr))

#define LDSM4T(r0, r1, r2, r3, addr)                                        \
    asm volatile("ldmatrix.sync.aligned.m8n8.x4.trans.shared.b16 "          \
                 "{%0,%1,%2,%3}, [%4];"                                     \
                 : "=r"(r0), "=r"(r1), "=r"(r2), "=r"(r3) : "r"(addr))

#define MMA_F16(d, a, b)                                                    \
    asm volatile(                                                           \
        "mma.sync.aligned.m16n8k16.row.col.f32.f16.f16.f32 "                \
        "{%0,%1,%2,%3}, {%4,%5,%6,%7}, {%8,%9}, {%0,%1,%2,%3};"             \
        : "+f"((d)[0]), "+f"((d)[1]), "+f"((d)[2]), "+f"((d)[3])            \
        : "r"((a)[0]), "r"((a)[1]), "r"((a)[2]), "r"((a)[3]),               \
          "r"((b)[0]), "r"((b)[1]))

// ---------------------------------------------------------------------------
// f32 -> f16 conversion (weights pre-pass)
// ---------------------------------------------------------------------------
__global__ __launch_bounds__(256)
void cvt_k(const float* __restrict__ s, __half* __restrict__ d)
{
    const int i = blockIdx.x * 256 + threadIdx.x;
    const float4 v = ((const float4*)s)[i];
    __half2* dp = (__half2*)d + 2 * (size_t)i;
    dp[0] = __floats2half2_rn(v.x, v.y);
    dp[1] = __floats2half2_rn(v.z, v.w);
}

// ---------------------------------------------------------------------------
// LayerNorm: one block per token row (1024 elems); writes fp16
// ---------------------------------------------------------------------------
__global__ __launch_bounds__(256)
void ln_k(const float* __restrict__ x, const float* __restrict__ g,
          const float* __restrict__ b, __half* __restrict__ out)
{
    const int row = blockIdx.x;
    const int tid = threadIdx.x;
    const float4 v = *(const float4*)(x + (size_t)row * D_ + tid * 4);

    float s = v.x + v.y + v.z + v.w;
    float q = v.x * v.x + v.y * v.y + v.z * v.z + v.w * v.w;
    #pragma unroll
    for (int o = 16; o > 0; o >>= 1) {
        s += __shfl_down_sync(0xffffffffu, s, o);
        q += __shfl_down_sync(0xffffffffu, q, o);
    }
    __shared__ float ss[8], sq[8];
    const int w = tid >> 5, ln = tid & 31;
    if (ln == 0) { ss[w] = s; sq[w] = q; }
    __syncthreads();
    float S = 0.f, Q = 0.f;
    #pragma unroll
    for (int i = 0; i < 8; i++) { S += ss[i]; Q += sq[i]; }

    const float mu  = S * (1.f / D_);
    const float var = Q * (1.f / D_) - mu * mu;
    const float rs  = rsqrtf(var + 1e-5f);

    const float4 gv = *(const float4*)(g + tid * 4);
    const float4 bv = *(const float4*)(b + tid * 4);
    __half2 h0 = __floats2half2_rn((v.x - mu) * rs * gv.x + bv.x,
                                   (v.y - mu) * rs * gv.y + bv.y);
    __half2 h1 = __floats2half2_rn((v.z - mu) * rs * gv.z + bv.z,
                                   (v.w - mu) * rs * gv.w + bv.w);
    __half2* op = (__half2*)(out + (size_t)row * D_) + tid * 2;
    op[0] = h0;
    op[1] = h1;
}

// ---------------------------------------------------------------------------
// Epilogue helper: consume one float2 at (m, n), n even.
//   EPI 0: scatter QKV: q -> fp16 scratch (scaled); k,v -> present (f32) +
//          fp16 scratch copies
//   EPI 1: C = acc + bias + resid (f32)
//   EPI 2: Ch = gelu(acc + bias) (f16)
// ---------------------------------------------------------------------------
template <int EPI>
__device__ __forceinline__ void epi_store(
    int m, int n, float2 v, int N,
    const float* __restrict__ bias, const float* __restrict__ resid,
    float* __restrict__ C, __half* __restrict__ Ch,
    float* __restrict__ kf, float* __restrict__ vf,
    __half* __restrict__ hq, __half* __restrict__ hk, __half* __restrict__ hv)
{
    const float2 bv = *(const float2*)(bias + n);
    v.x += bv.x;
    v.y += bv.y;
    if (EPI == 0) {
        const int part = n >> 10;
        const int d    = n & 1023;
        const int hh   = d >> 6;
        const int hd   = d & 63;
        const int l    = m >> 1;     // token m = l*B + b, B=2
        const int bb   = m & 1;
        const size_t idx = (((size_t)(bb * H_ + hh) * L_) + l) * HD_ + hd;
        if (part == 0) {
            *(__half2*)(hq + idx) = __floats2half2_rn(v.x * SCQ, v.y * SCQ);
        } else if (part == 1) {
            *(float2*)(kf + idx) = v;
            *(__half2*)(hk + idx) = __floats2half2_rn(v.x, v.y);
        } else {
            *(float2*)(vf + idx) = v;
            *(__half2*)(hv + idx) = __floats2half2_rn(v.x, v.y);
        }
    } else if (EPI == 1) {
        const size_t idx = (size_t)m * N + n;
        const float2 rv = *(const float2*)(resid + idx);
        v.x += rv.x;
        v.y += rv.y;
        *(float2*)(C + idx) = v;
    } else {
        const float t0 = tanhf(0.7978845608028654f *
                               (v.x + 0.044715f * v.x * v.x * v.x));
        const float t1 = tanhf(0.7978845608028654f *
                               (v.y + 0.044715f * v.y * v.y * v.y));
        *(__half2*)(Ch + (size_t)m * N + n) =
            __floats2half2_rn(0.5f * v.x * (1.f + t0), 0.5f * v.y * (1.f + t1));
    }
}

// ---------------------------------------------------------------------------
// fp16 GEMM, 3-stage cp.async pipeline (ONE __syncthreads per K-tile).
// CTA 128x128, BK=32, 256 threads (8 warps 4x2, warp tile 32x64).
// Smem ring: 3 x { As 128x40 halfs (80B stride, 16B-aligned rows),
//                  Bs 32x136 halfs (272B stride) } = 56.8 KB dynamic.
// NOTE: A row stride MUST be a multiple of 8 halfs (16B) for cp.async.
// ---------------------------------------------------------------------------
#define ASTR 40
#define BSTR 136
#define ABYTES (128 * ASTR * 2)
#define BBYTES (32 * BSTR * 2)
#define STG_BYTES (ABYTES + BBYTES)
#define GEMM_SMEM (3 * STG_BYTES)

template <int EPI>
__global__ __launch_bounds__(256, 2)
void hgemm_k(const __half* __restrict__ A, const __half* __restrict__ Bm,
             const float* __restrict__ bias, const float* __restrict__ resid,
             float* __restrict__ C, __half* __restrict__ Ch, int M, int N, int K,
             float* __restrict__ kf, float* __restrict__ vf,
             __half* __restrict__ hq, __half* __restrict__ hk, __half* __restrict__ hv)
{
    constexpr int BM = 128, BN = 128, BK = 32;
    extern __shared__ __align__(16) char dyn[];

    const int tid  = threadIdx.x;
    const int wid  = tid >> 5;
    const int lane = tid & 31;
    const int wm   = (wid & 3) * 32;
    const int wn   = (wid >> 2) * 64;
    const int gid  = lane >> 2;
    const int tg   = lane & 3;
    const int cCol = blockIdx.x, cRow = blockIdx.y;

    const __half* Abase = A  + (size_t)cRow * BM * K;
    const __half* Bbase = Bm + (size_t)cCol * BN;

    // cp.async writer coords
    const int arow = tid >> 1;                 // 0..127
    const int ac0  = (tid & 1) * 2;            // chunks {0,1} or {2,3} (8 halfs)
    const int brow = tid >> 4;                 // 0..15 (+16)
    const int bc   = tid & 15;                 // 16 chunks per B row
    const uint32_t s0 = smem_u32(dyn);

    // ldmatrix reader lane offsets
    const int a_r  = lane & 15;
    const int a_c  = (lane >> 4) * 8;
    const int b_k  = lane & 15;
    const int b_n  = (lane >> 4) * 8;

    float acc[2][8][4];
    #pragma unroll
    for (int mt = 0; mt < 2; mt++)
        #pragma unroll
        for (int nt = 0; nt < 8; nt++)
            #pragma unroll
            for (int i = 0; i < 4; i++) acc[mt][nt][i] = 0.f;

    const int NT = K / BK;

    // prologue: stages 0, 1
    #pragma unroll
    for (int p = 0; p < 2; p++) {
        const int k0 = p * BK;
        const uint32_t dA = s0 + p * STG_BYTES;
        const uint32_t dB = dA + ABYTES;
        cpa16(dA + (arow * ASTR + (ac0    ) * 8) * 2, Abase + (size_t)arow * K + k0 + (ac0    ) * 8);
        cpa16(dA + (arow * ASTR + (ac0 + 1) * 8) * 2, Abase + (size_t)arow * K + k0 + (ac0 + 1) * 8);
        cpa16(dB + ((brow     ) * BSTR + bc * 8) * 2, Bbase + (size_t)(k0 + brow     ) * N + bc * 8);
        cpa16(dB + ((brow + 16) * BSTR + bc * 8) * 2, Bbase + (size_t)(k0 + brow + 16) * N + bc * 8);
        asm volatile("cp.async.commit_group;");
    }

    int stg = 0;           // t % 3
    int pstg = 2;          // (t+2) % 3
    for (int t = 0; t < NT; t++) {
        asm volatile("cp.async.wait_group 1;");
        __syncthreads();

        // prefetch tile t+2 into stage (t+2)%3 (free: reads finished at t-1)
        if (t + 2 < NT) {
            const int k0 = (t + 2) * BK;
            const uint32_t dA = s0 + pstg * STG_BYTES;
            const uint32_t dB = dA + ABYTES;
            cpa16(dA + (arow * ASTR + (ac0    ) * 8) * 2, Abase + (size_t)arow * K + k0 + (ac0    ) * 8);
            cpa16(dA + (arow * ASTR + (ac0 + 1) * 8) * 2, Abase + (size_t)arow * K + k0 + (ac0 + 1) * 8);
            cpa16(dB + ((brow     ) * BSTR + bc * 8) * 2, Bbase + (size_t)(k0 + brow     ) * N + bc * 8);
            cpa16(dB + ((brow + 16) * BSTR + bc * 8) * 2, Bbase + (size_t)(k0 + brow + 16) * N + bc * 8);
        }
        asm volatile("cp.async.commit_group;");   // possibly empty: keeps count

        const uint32_t aS = s0 + stg * STG_BYTES;
        const uint32_t bS = aS + ABYTES;

        #pragma unroll
        for (int ks = 0; ks < 2; ks++) {
            uint32_t af[2][4];
            #pragma unroll
            for (int mt = 0; mt < 2; mt++) {
                const uint32_t addr =
                    aS + ((wm + mt * 16 + a_r) * ASTR + ks * 16 + a_c) * 2;
                LDSM4(af[mt][0], af[mt][1], af[mt][2], af[mt][3], addr);
            }
            uint32_t bf[8][2];
            #pragma unroll
            for (int ng = 0; ng < 4; ng++) {
                const uint32_t addr =
                    bS + ((ks * 16 + b_k) * BSTR + wn + ng * 16 + b_n) * 2;
                LDSM4T(bf[2 * ng][0], bf[2 * ng][1],
                       bf[2 * ng + 1][0], bf[2 * ng + 1][1], addr);
            }
            #pragma unroll
            for (int mt = 0; mt < 2; mt++)
                #pragma unroll
                for (int nt = 0; nt < 8; nt++)
                    MMA_F16(acc[mt][nt], af[mt], bf[nt]);
        }

        stg  = (stg == 2)  ? 0 : stg + 1;
        pstg = (pstg == 2) ? 0 : pstg + 1;
    }

    // epilogue (m16n8 C-fragment layout)
    #pragma unroll
    for (int mt = 0; mt < 2; mt++) {
        const int m0 = cRow * BM + wm + mt * 16 + gid;
        #pragma unroll
        for (int nt = 0; nt < 8; nt++) {
            const int n0 = cCol * BN + wn + nt * 8 + tg * 2;
            epi_store<EPI>(m0,     n0, make_float2(acc[mt][nt][0], acc[mt][nt][1]),
                           N, bias, resid, C, Ch, kf, vf, hq, hk, hv);
            epi_store<EPI>(m0 + 8, n0, make_float2(acc[mt][nt][2], acc[mt][nt][3]),
                           N, bias, resid, C, Ch, kf, vf, hq, hk, hv);
        }
    }
}

// ---------------------------------------------------------------------------
// fp16 flash attention. CTA: 128 q-rows x one (b,h), 8 warps x 16 q-rows.
// Q frags fp16 in regs (pre-scaled). KV fp16 tiles of 32, double-buffered.
// QK^T: ldmatrix (non-trans) on K rows. PV: P packed straight from S
// C-fragments (no shuffles), V via ldmatrix.trans.
// ---------------------------------------------------------------------------
#define KVT 32
#define NTILES (L_ / KVT)
#define KVSTR 72   // halfs; 144B row stride (16B multiple)

__global__ __launch_bounds__(256, 2)
void attn_mma_k(const __half* __restrict__ q, const __half* __restrict__ k,
                const __half* __restrict__ v, __half* __restrict__ out)
{
    __shared__ __half Ks[2][KVT][KVSTR];
    __shared__ __half Vs[2][KVT][KVSTR];

    const int bh   = blockIdx.y;
    const int b    = bh >> 4;
    const int h    = bh & 15;
    const int tid  = threadIdx.x;
    const int wid  = tid >> 5;
    const int lane = tid & 31;
    const int gid  = lane >> 2;
    const int tg   = lane & 3;

    const __half* kbase = k + (size_t)bh * L_ * HD_;
    const __half* vbase = v + (size_t)bh * L_ * HD_;

    // cp.async writer coords: 32 rows x 8 chunks(16B) per matrix, 1/thread
    const int ld_r = tid >> 3;            // 0..31
    const int ld_c = (tid & 7) * 8;       // half offset
    const uint32_t sK0 = smem_u32(&Ks[0][0][0]);
    const uint32_t sV0 = smem_u32(&Vs[0][0][0]);

    // ldmatrix lane offsets
    const int k_row = (lane & 7) + ((lane >> 4) & 1) * 8;  // within 16-row pair
    const int k_col = ((lane >> 3) & 1) * 8;               // k-half
    const int v_row = lane & 15;
    const int v_col = (lane >> 4) * 8;

    // Q fragments (fp16, pre-scaled by log2(e)/8 at QKV epilogue)
    const int qr = blockIdx.x * 128 + wid * 16 + gid;
    const __half* qp = q + (size_t)bh * L_ * HD_;
    uint32_t qf[4][4];
    #pragma unroll
    for (int kq = 0; kq < 4; kq++) {
        qf[kq][0] = *(const uint32_t*)(qp + (size_t)qr       * HD_ + kq * 16 + 2 * tg);
        qf[kq][1] = *(const uint32_t*)(qp + (size_t)(qr + 8) * HD_ + kq * 16 + 2 * tg);
        qf[kq][2] = *(const uint32_t*)(qp + (size_t)qr       * HD_ + kq * 16 + 8 + 2 * tg);
        qf[kq][3] = *(const uint32_t*)(qp + (size_t)(qr + 8) * HD_ + kq * 16 + 8 + 2 * tg);
    }

    float oacc[8][4];
    #pragma unroll
    for (int on = 0; on < 8; on++)
        #pragma unroll
        for (int i = 0; i < 4; i++) oacc[on][i] = 0.f;
    float mr0 = -1e30f, mr1 = -1e30f, ls0 = 0.f, ls1 = 0.f;

    {
        cpa16(sK0 + (ld_r * KVSTR + ld_c) * 2, kbase + (size_t)ld_r * HD_ + ld_c);
        cpa16(sV0 + (ld_r * KVSTR + ld_c) * 2, vbase + (size_t)ld_r * HD_ + ld_c);
        asm volatile("cp.async.commit_group;");
    }

    for (int t = 0; t < NTILES; t++) {
        const int cur = t & 1;
        if (t + 1 < NTILES) {
            const int nb = (t + 1) & 1;
            const __half* ksrc = kbase + (size_t)(t + 1) * KVT * HD_;
            const __half* vsrc = vbase + (size_t)(t + 1) * KVT * HD_;
            cpa16(sK0 + (nb * KVT * KVSTR + ld_r * KVSTR + ld_c) * 2,
                  ksrc + (size_t)ld_r * HD_ + ld_c);
            cpa16(sV0 + (nb * KVT * KVSTR + ld_r * KVSTR + ld_c) * 2,
                  vsrc + (size_t)ld_r * HD_ + ld_c);
            asm volatile("cp.async.commit_group;");
            asm volatile("cp.async.wait_group 1;");
        } else {
            asm volatile("cp.async.wait_group 0;");
        }
        __syncthreads();

        // ---- S = Q @ K^T : warp's 16 q-rows x 32 kv ----
        float sacc[4][4];
        #pragma unroll
        for (int nt = 0; nt < 4; nt++)
            #pragma unroll
            for (int i = 0; i < 4; i++) sacc[nt][i] = 0.f;

        const uint32_t kS = sK0 + cur * (KVT * KVSTR * 2);
        #pragma unroll
        for (int ks = 0; ks < 4; ks++) {
            uint32_t bf[4][2];
            #pragma unroll
            for (int p = 0; p < 2; p++) {   // kv row pairs 0-15, 16-31
                const uint32_t addr =
                    kS + ((p * 16 + k_row) * KVSTR + ks * 16 + k_col) * 2;
                LDSM4(bf[2 * p][0], bf[2 * p][1],
                      bf[2 * p + 1][0], bf[2 * p + 1][1], addr);
            }
            #pragma unroll
            for (int nt = 0; nt < 4; nt++)
                MMA_F16(sacc[nt], qf[ks], bf[nt]);
        }

        // ---- online softmax (base 2; scale folded into q) ----
        float m0 = mr0, m1 = mr1;
        #pragma unroll
        for (int nt = 0; nt < 4; nt++) {
            m0 = fmaxf(m0, fmaxf(sacc[nt][0], sacc[nt][1]));
            m1 = fmaxf(m1, fmaxf(sacc[nt][2], sacc[nt][3]));
        }
        m0 = fmaxf(m0, __shfl_xor_sync(0xffffffffu, m0, 1));
        m0 = fmaxf(m0, __shfl_xor_sync(0xffffffffu, m0, 2));
        m1 = fmaxf(m1, __shfl_xor_sync(0xffffffffu, m1, 1));
        m1 = fmaxf(m1, __shfl_xor_sync(0xffffffffu, m1, 2));

        const float sc0 = ex2f(mr0 - m0);
        const float sc1 = ex2f(mr1 - m1);
        mr0 = m0; mr1 = m1;

        float rs0 = 0.f, rs1 = 0.f;
        #pragma unroll
        for (int nt = 0; nt < 4; nt++) {
            sacc[nt][0] = ex2f(sacc[nt][0] - m0);
            sacc[nt][1] = ex2f(sacc[nt][1] - m0);
            sacc[nt][2] = ex2f(sacc[nt][2] - m1);
            sacc[nt][3] = ex2f(sacc[nt][3] - m1);
            rs0 += sacc[nt][0] + sacc[nt][1];
            rs1 += sacc[nt][2] + sacc[nt][3];
        }
        rs0 += __shfl_xor_sync(0xffffffffu, rs0, 1);
        rs0 += __shfl_xor_sync(0xffffffffu, rs0, 2);
        rs1 += __shfl_xor_sync(0xffffffffu, rs1, 1);
        rs1 += __shfl_xor_sync(0xffffffffu, rs1, 2);
        ls0 = ls0 * sc0 + rs0;
        ls1 = ls1 * sc1 + rs1;

        #pragma unroll
        for (int on = 0; on < 8; on++) {
            oacc[on][0] *= sc0;
            oacc[on][1] *= sc0;
            oacc[on][2] *= sc1;
            oacc[on][3] *= sc1;
        }

        // ---- O += P @ V : P packed directly from S fragments ----
        const uint32_t vS = sV0 + cur * (KVT * KVSTR * 2);
        #pragma unroll
        for (int kb = 0; kb < 2; kb++) {     // two k16 blocks of kv
            uint32_t af[4];
            af[0] = pkh(sacc[2 * kb][0],     sacc[2 * kb][1]);
            af[1] = pkh(sacc[2 * kb][2],     sacc[2 * kb][3]);
            af[2] = pkh(sacc[2 * kb + 1][0], sacc[2 * kb + 1][1]);
            af[3] = pkh(sacc[2 * kb + 1][2], sacc[2 * kb + 1][3]);
            #pragma unroll
            for (int og = 0; og < 4; og++) { // hd 16-col groups
                uint32_t vf2[4];
                const uint32_t addr =
                    vS + ((kb * 16 + v_row) * KVSTR + og * 16 + v_col) * 2;
                LDSM4T(vf2[0], vf2[1], vf2[2], vf2[3], addr);
                MMA_F16(oacc[2 * og],     af, (vf2 + 0));
                MMA_F16(oacc[2 * og + 1], af, (vf2 + 2));
            }
        }
        __syncthreads();
    }

    const float inv0 = 1.f / ls0;
    const float inv1 = 1.f / ls1;
    __half* op0 = out + ((size_t)qr       * B_ + b) * D_ + h * HD_;
    __half* op1 = out + ((size_t)(qr + 8) * B_ + b) * D_ + h * HD_;
    #pragma unroll
    for (int on = 0; on < 8; on++) {
        const int c0 = on * 8 + tg * 2;
        *(__half2*)(op0 + c0) =
            __floats2half2_rn(oacc[on][0] * inv0, oacc[on][1] * inv0);
        *(__half2*)(op1 + c0) =
            __floats2half2_rn(oacc[on][2] * inv1, oacc[on][3] * inv1);
    }
}

// ---------------------------------------------------------------------------
// Launch
// ---------------------------------------------------------------------------
extern "C" void kernel_launch(void* const* d_in, const int* in_sizes, int n_in,
                              void* d_out, int out_size)
{
    const float* x      = (const float*)d_in[0];
    const float* ln1_g  = (const float*)d_in[1];
    const float* ln1_b  = (const float*)d_in[2];
    const float* w_attn = (const float*)d_in[3];
    const float* b_attn = (const float*)d_in[4];
    const float* w_proj = (const float*)d_in[5];
    const float* b_proj = (const float*)d_in[6];
    const float* ln2_g  = (const float*)d_in[7];
    const float* ln2_b  = (const float*)d_in[8];
    const float* w_fc   = (const float*)d_in[9];
    const float* b_fc   = (const float*)d_in[10];
    const float* w_out  = (const float*)d_in[11];
    const float* b_out  = (const float*)d_in[12];

    float* out  = (float*)d_out;
    float* kout = out  + (size_t)L_ * B_ * D_;                 // present[0]
    float* vout = kout + (size_t)B_ * H_ * L_ * HD_;           // present[1]

    __half *h16, *at16, *m16, *w16, *q16, *k16, *v16;
    float *x1ptr;
    cudaGetSymbolAddress((void**)&h16,  g_h16);
    cudaGetSymbolAddress((void**)&at16, g_at16);
    cudaGetSymbolAddress((void**)&m16,  g_m16);
    cudaGetSymbolAddress((void**)&w16,  g_w16);
    cudaGetSymbolAddress((void**)&q16,  g_q16);
    cudaGetSymbolAddress((void**)&k16,  g_k16);
    cudaGetSymbolAddress((void**)&v16,  g_v16);
    cudaGetSymbolAddress((void**)&x1ptr, g_x1);

    // enable 56.8KB dynamic smem for GEMMs (host attr call; not a stream op)
    static int attr_done = 0;
    if (!attr_done) {
        cudaFuncSetAttribute(hgemm_k<0>, cudaFuncAttributeMaxDynamicSharedMemorySize, GEMM_SMEM);
        cudaFuncSetAttribute(hgemm_k<1>, cudaFuncAttributeMaxDynamicSharedMemorySize, GEMM_SMEM);
        cudaFuncSetAttribute(hgemm_k<2>, cudaFuncAttributeMaxDynamicSharedMemorySize, GEMM_SMEM);
        attr_done = 1;
    }

    // 0) weights -> fp16
    cvt_k<<<3 * 1024 * 1024 / 1024, 256>>>(w_attn, w16 + WA_OFF);
    cvt_k<<<1024 * 1024 / 1024,     256>>>(w_proj, w16 + WP_OFF);
    cvt_k<<<4 * 1024 * 1024 / 1024, 256>>>(w_fc,   w16 + WF_OFF);
    cvt_k<<<4 * 1024 * 1024 / 1024, 256>>>(w_out,  w16 + WO_OFF);

    // 1) LN1 -> fp16
    ln_k<<<MTOK, 256>>>(x, ln1_g, ln1_b, h16);

    // 2) QKV GEMM; q->fp16 scratch, k/v->present(f32)+fp16 scratch
    hgemm_k<0><<<dim3(3 * D_ / 128, MTOK / 128), 256, GEMM_SMEM>>>(
        h16, w16 + WA_OFF, b_attn, nullptr, nullptr, nullptr, MTOK, 3 * D_, D_,
        kout, vout, q16, k16, v16);

    // 3) fp16 attention -> fp16 token-major
    attn_mma_k<<<dim3(L_ / 128, B_ * H_), 256>>>(q16, k16, v16, at16);

    // 4) proj + residual -> x1 (f32)
    hgemm_k<1><<<dim3(D_ / 128, MTOK / 128), 256, GEMM_SMEM>>>(
        at16, w16 + WP_OFF, b_proj, x, x1ptr, nullptr, MTOK, D_, D_,
        nullptr, nullptr, nullptr, nullptr, nullptr);

    // 5) LN2 -> fp16
    ln_k<<<MTOK, 256>>>(x1ptr, ln2_g, ln2_b, h16);

    // 6) FC + GELU -> fp16
    hgemm_k<2><<<dim3(DFF_ / 128, MTOK / 128), 256, GEMM_SMEM>>>(
        h16, w16 + WF_OFF, b_fc, nullptr, nullptr, m16, MTOK, DFF_, D_,
        nullptr, nullptr, nullptr, nullptr, nullptr);

    // 7) out proj + residual -> final x (f32)
    hgemm_k<1><<<dim3(D_ / 128, MTOK / 128), 256, GEMM_SMEM>>>(
        m16, w16 + WO_OFF, b_out, x1ptr, out, nullptr, MTOK, D_, DFF_,
        nullptr, nullptr, nullptr, nullptr, nullptr);
}